// round 15
// baseline (speedup 1.0000x reference)
#include <cuda_runtime.h>
#include <cuda_bf16.h>
#include <mma.h>
#include <math.h>
#include <stdint.h>

using namespace nvcuda;

#define NN 50000
#define NPAD 50048
#define EE 800000
#define HID 128

// ---------------- scratch (no allocation allowed) ----------------
__device__ float g_buf[(size_t)8 * NPAD * HID];
__device__ int g_ibuf[NN + (NN + 1) + NN + EE + 64];
#define WTOT 278528
__device__ __align__(16) __nv_bfloat16 g_whi[WTOT];
__device__ __align__(16) __nv_bfloat16 g_wlo[WTOT];

__device__ __forceinline__ float gelu_tanh(float x) {
    float x3 = x * x * x;
    float t = tanhf(0.7978845608028654f * (x + 0.044715f * x3));
    return 0.5f * x * (1.0f + t);
}

__device__ __forceinline__ uint32_t smem_u32(const void* p) {
    uint32_t a;
    asm("{ .reg .u64 t; cvta.to.shared.u64 t, %1; cvt.u32.u64 %0, t; }" : "=r"(a) : "l"(p));
    return a;
}
__device__ __forceinline__ void cp_async16(uint32_t dst, const void* src) {
    asm volatile("cp.async.cg.shared.global [%0], [%1], 16;" :: "r"(dst), "l"(src));
}
#define CP_COMMIT() asm volatile("cp.async.commit_group;" ::: "memory")
#define CP_WAIT0()  asm volatile("cp.async.wait_group 0;" ::: "memory")
#define CP_WAIT1()  asm volatile("cp.async.wait_group 1;" ::: "memory")

// ---------------- CSR build ----------------
__global__ void hist_kernel(const int* __restrict__ dst, int* __restrict__ deg, int E) {
    int e = blockIdx.x * blockDim.x + threadIdx.x;
    if (e < E) atomicAdd(&deg[dst[e]], 1);
}

__global__ void scan_part_kernel(const int* __restrict__ deg, int* __restrict__ part, int n) {
    __shared__ int ws[32];
    const int lane = threadIdx.x & 31, wid = threadIdx.x >> 5;
    int i = blockIdx.x * 1024 + threadIdx.x;
    int v = (i < n) ? deg[i] : 0;
#pragma unroll
    for (int o = 16; o; o >>= 1) v += __shfl_xor_sync(0xffffffffu, v, o);
    if (lane == 0) ws[wid] = v;
    __syncthreads();
    if (wid == 0) {
        int x = ws[lane];
#pragma unroll
        for (int o = 16; o; o >>= 1) x += __shfl_xor_sync(0xffffffffu, x, o);
        if (lane == 0) part[blockIdx.x] = x;
    }
}

__global__ void scan_off_kernel(int* __restrict__ part, int nb) {
    int lane = threadIdx.x;
    int v0 = (2 * lane < nb) ? part[2 * lane] : 0;
    int v1 = (2 * lane + 1 < nb) ? part[2 * lane + 1] : 0;
    int sum = v0 + v1;
    int x = sum;
#pragma unroll
    for (int o = 1; o < 32; o <<= 1) {
        int t = __shfl_up_sync(0xffffffffu, x, o);
        if (lane >= o) x += t;
    }
    int excl = x - sum;
    if (2 * lane < nb) part[2 * lane] = excl;
    if (2 * lane + 1 < nb) part[2 * lane + 1] = excl + v0;
}

__global__ void scan_final_kernel(const int* __restrict__ deg, const int* __restrict__ part,
                                  int* __restrict__ row_ptr, int* __restrict__ cur, int n) {
    __shared__ int wsum[32];
    const int lane = threadIdx.x & 31, wid = threadIdx.x >> 5;
    int i = blockIdx.x * 1024 + threadIdx.x;
    int v = (i < n) ? deg[i] : 0;
    int x = v;
#pragma unroll
    for (int o = 1; o < 32; o <<= 1) {
        int t = __shfl_up_sync(0xffffffffu, x, o);
        if (lane >= o) x += t;
    }
    if (lane == 31) wsum[wid] = x;
    __syncthreads();
    if (wid == 0) {
        int y = wsum[lane];
#pragma unroll
        for (int o = 1; o < 32; o <<= 1) {
            int t = __shfl_up_sync(0xffffffffu, y, o);
            if (lane >= o) y += t;
        }
        wsum[lane] = y;
    }
    __syncthreads();
    int off = part[blockIdx.x] + (wid > 0 ? wsum[wid - 1] : 0);
    if (i < n) {
        row_ptr[i + 1] = off + x;
        cur[i] = off + x - v;
    }
    if (i == 0) row_ptr[0] = 0;
}

__global__ void scatter_kernel(const int* __restrict__ src, const int* __restrict__ dst,
                               int* __restrict__ cur, int* __restrict__ csr_src, int E) {
    int e = blockIdx.x * blockDim.x + threadIdx.x;
    if (e < E) {
        int p = atomicAdd(&cur[dst[e]], 1);
        csr_src[p] = src[e];
    }
}

// ---------------- weight transpose + bf16 split (range [lo, hi)) -----------
__global__ void wconv_kernel(
    const float* __restrict__ Wi,
    const float* __restrict__ Wsd, const float* __restrict__ Wdd,
    const float* __restrict__ Wsm, const float* __restrict__ Wdm,
    const float* __restrict__ Wsu, const float* __restrict__ Wdu,
    const float* __restrict__ Wf,
    __nv_bfloat16* __restrict__ bhi, __nv_bfloat16* __restrict__ blo,
    int lo, int hi)
{
    int idx = lo + blockIdx.x * blockDim.x + threadIdx.x;
    if (idx >= hi) return;
    int base, K; const float *S, *D2;
    if (idx < 32768)       { base = 0;      K = 256; S = Wi;           D2 = nullptr; }
    else if (idx < 65536)  { base = 32768;  K = 128; S = Wsd;          D2 = Wdd; }
    else if (idx < 98304)  { base = 65536;  K = 128; S = Wsd + 16384;  D2 = Wdd + 16384; }
    else if (idx < 131072) { base = 98304;  K = 128; S = Wsm;          D2 = Wdm; }
    else if (idx < 196608) { base = 131072; K = 256; S = Wsu;          D2 = Wdu; }
    else if (idx < 262144) { base = 196608; K = 256; S = Wsu + 32768;  D2 = Wdu + 32768; }
    else                   { base = 262144; K = 128; S = Wf;           D2 = nullptr; }
    int local = idx - base;
    int n = local / K, k = local - n * K;
    const float* W = (D2 && n >= 128) ? D2 : S;
    int nc = (D2 && n >= 128) ? n - 128 : n;
    float x = W[(size_t)k * 128 + nc];
    __nv_bfloat16 h = __float2bfloat16_rn(x);
    bhi[idx] = h;
    blo[idx] = __float2bfloat16_rn(x - __bfloat162float(h));
}

// ================= tgemm_fast: A bf16 hi/lo, full cp.async, 3-stage =========
#define STG 61440
#define SAH 0
#define SAL 10240
#define SBH 20480
#define SBL 40960
#define TGF_DSM (3 * STG)

template<int NB>
__global__ __launch_bounds__(512) void tgemm_fast(
    const __nv_bfloat16* __restrict__ Ahi1, const __nv_bfloat16* __restrict__ Alo1,
    const __nv_bfloat16* __restrict__ Ahi2, const __nv_bfloat16* __restrict__ Alo2,
    const __nv_bfloat16* __restrict__ Bhi, const __nv_bfloat16* __restrict__ Blo,
    const float* __restrict__ bias,
    float* __restrict__ Ca, float* __restrict__ Cb,
    int M, int K)
{
    extern __shared__ char dsm[];
    const uint32_t sb = smem_u32(dsm);
    const int tid = threadIdx.x;
    const int wid = tid >> 5, lane = tid & 31;
    const int rowBase = blockIdx.x * 128;

    __shared__ float sBias[128];
    if (NB == 1 && tid < 128) sBias[tid] = bias[tid];

    auto cpAll = [&](int st, int c) {
        {
            const __nv_bfloat16* Ah = (c < 4) ? Ahi1 : Ahi2;
            const __nv_bfloat16* Al = (c < 4) ? Alo1 : Alo2;
            int cc = c & 3;
            int r = tid >> 2, q = tid & 3;
            size_t so = (size_t)(rowBase + r) * 128 + cc * 32 + q * 8;
            uint32_t d = sb + st * STG + r * 80 + (q << 4);
            cp_async16(d + SAH, Ah + so);
            cp_async16(d + SAL, Al + so);
        }
        if (NB == 2) {
            int r = tid >> 1, q0 = (tid & 1) << 1;
#pragma unroll
            for (int dq = 0; dq < 2; dq++) {
                int q = q0 + dq;
                uint32_t d = sb + st * STG + r * 80 + (q << 4);
                cp_async16(d + SBH, Bhi + (size_t)r * K + (c << 5) + (q << 3));
                cp_async16(d + SBL, Blo + (size_t)r * K + (c << 5) + (q << 3));
            }
        } else {
            int r = tid >> 2, q = tid & 3;
            uint32_t d = sb + st * STG + r * 80 + (q << 4);
            cp_async16(d + SBH, Bhi + (size_t)r * K + (c << 5) + (q << 3));
            cp_async16(d + SBL, Blo + (size_t)r * K + (c << 5) + (q << 3));
        }
    };

    const int nCh = K >> 5;

    cpAll(0, 0); CP_COMMIT();
    if (nCh > 1) { cpAll(1, 1); CP_COMMIT(); }

    if (NB == 2) {
        const int rowg = wid & 3;
        const int colh = (wid >> 2) & 1;
        const int hb   = wid >> 3;
        wmma::fragment<wmma::accumulator, 16, 16, 16, float> acc[8];
#pragma unroll
        for (int t = 0; t < 8; t++) wmma::fill_fragment(acc[t], 0.0f);

        for (int c = 0; c < nCh; c++) {
            if (c + 1 == nCh) { CP_WAIT0(); } else { CP_WAIT1(); }
            __syncthreads();
            const int st = c % 3;
            const __nv_bfloat16* ah_base = reinterpret_cast<const __nv_bfloat16*>(dsm + st * STG + SAH);
            const __nv_bfloat16* al_base = reinterpret_cast<const __nv_bfloat16*>(dsm + st * STG + SAL);
            const __nv_bfloat16* bh_base = reinterpret_cast<const __nv_bfloat16*>(dsm + st * STG + SBH);
            const __nv_bfloat16* bl_base = reinterpret_cast<const __nv_bfloat16*>(dsm + st * STG + SBL);
#pragma unroll
            for (int ks = 0; ks < 32; ks += 16) {
                wmma::fragment<wmma::matrix_a, 16, 16, 16, __nv_bfloat16, wmma::row_major> ah0, ah1, al0, al1;
                wmma::load_matrix_sync(ah0, ah_base + (rowg * 32) * 40 + ks, 40);
                wmma::load_matrix_sync(ah1, ah_base + (rowg * 32 + 16) * 40 + ks, 40);
                wmma::load_matrix_sync(al0, al_base + (rowg * 32) * 40 + ks, 40);
                wmma::load_matrix_sync(al1, al_base + (rowg * 32 + 16) * 40 + ks, 40);
#pragma unroll
                for (int t = 0; t < 4; t++) {
                    int brow = hb * 128 + colh * 64 + t * 16;
                    wmma::fragment<wmma::matrix_b, 16, 16, 16, __nv_bfloat16, wmma::col_major> bh, bl;
                    wmma::load_matrix_sync(bh, bh_base + brow * 40 + ks, 40);
                    wmma::load_matrix_sync(bl, bl_base + brow * 40 + ks, 40);
                    wmma::mma_sync(acc[t], ah0, bh, acc[t]);
                    wmma::mma_sync(acc[t], ah0, bl, acc[t]);
                    wmma::mma_sync(acc[t], al0, bh, acc[t]);
                    wmma::mma_sync(acc[4 + t], ah1, bh, acc[4 + t]);
                    wmma::mma_sync(acc[4 + t], ah1, bl, acc[4 + t]);
                    wmma::mma_sync(acc[4 + t], al1, bh, acc[4 + t]);
                }
            }
            if (c + 2 < nCh) { cpAll((c + 2) % 3, c + 2); CP_COMMIT(); }
        }
        float* Cp = hb ? Cb : Ca;
#pragma unroll
        for (int s = 0; s < 2; s++) {
#pragma unroll
            for (int t = 0; t < 4; t++) {
                wmma::store_matrix_sync(
                    Cp + (size_t)(rowBase + rowg * 32 + s * 16) * 128 + colh * 64 + t * 16,
                    acc[s * 4 + t], 128, wmma::mem_row_major);
            }
        }
    } else {
        const int stripe = wid >> 1, colh = wid & 1;
        wmma::fragment<wmma::accumulator, 16, 16, 16, float> acc[4];
#pragma unroll
        for (int t = 0; t < 4; t++) wmma::fill_fragment(acc[t], 0.0f);

        for (int c = 0; c < nCh; c++) {
            if (c + 1 == nCh) { CP_WAIT0(); } else { CP_WAIT1(); }
            __syncthreads();
            const int st = c % 3;
            const __nv_bfloat16* ah_base = reinterpret_cast<const __nv_bfloat16*>(dsm + st * STG + SAH);
            const __nv_bfloat16* al_base = reinterpret_cast<const __nv_bfloat16*>(dsm + st * STG + SAL);
            const __nv_bfloat16* bh_base = reinterpret_cast<const __nv_bfloat16*>(dsm + st * STG + SBH);
            const __nv_bfloat16* bl_base = reinterpret_cast<const __nv_bfloat16*>(dsm + st * STG + SBL);
#pragma unroll
            for (int ks = 0; ks < 32; ks += 16) {
                wmma::fragment<wmma::matrix_a, 16, 16, 16, __nv_bfloat16, wmma::row_major> ah, al;
                wmma::load_matrix_sync(ah, ah_base + stripe * 16 * 40 + ks, 40);
                wmma::load_matrix_sync(al, al_base + stripe * 16 * 40 + ks, 40);
#pragma unroll
                for (int t = 0; t < 4; t++) {
                    int brow = colh * 64 + t * 16;
                    wmma::fragment<wmma::matrix_b, 16, 16, 16, __nv_bfloat16, wmma::col_major> bh, bl;
                    wmma::load_matrix_sync(bh, bh_base + brow * 40 + ks, 40);
                    wmma::load_matrix_sync(bl, bl_base + brow * 40 + ks, 40);
                    wmma::mma_sync(acc[t], ah, bh, acc[t]);
                    wmma::mma_sync(acc[t], ah, bl, acc[t]);
                    wmma::mma_sync(acc[t], al, bh, acc[t]);
                }
            }
            if (c + 2 < nCh) { cpAll((c + 2) % 3, c + 2); CP_COMMIT(); }
        }

        __syncthreads();
        float* sE = reinterpret_cast<float*>(dsm) + wid * 256;
#pragma unroll
        for (int t = 0; t < 4; t++) {
            int tg = colh * 4 + t;
            wmma::store_matrix_sync(sE, acc[t], 16, wmma::mem_row_major);
            __syncwarp();
#pragma unroll
            for (int i = 0; i < 8; i++) {
                int idx = i * 32 + lane;
                int row = idx >> 4, col = idx & 15;
                int r = rowBase + stripe * 16 + row;
                if (r < M) {
                    float vv = sE[idx] + sBias[tg * 16 + col];
                    Ca[(size_t)r * 128 + tg * 16 + col] = vv;
                }
            }
            __syncwarp();
        }
    }
}

// ================= tgemm_init: A fp32 (x_t | time_emb), out bf16 pair + gelu
#define STGI 40960
#define IAH 0
#define IAL 10240
#define IBH 20480
#define IBL 30720
#define TGI_DSM (2 * STGI)

__global__ __launch_bounds__(512) void tgemm_init(
    const float* __restrict__ A1, const float* __restrict__ A2,
    const __nv_bfloat16* __restrict__ Bhi, const __nv_bfloat16* __restrict__ Blo,
    const float* __restrict__ bias,
    __nv_bfloat16* __restrict__ Chi, __nv_bfloat16* __restrict__ Clo,
    int M)
{
    const int K = 256;
    extern __shared__ char dsm[];
    const uint32_t sb = smem_u32(dsm);
    const int tid = threadIdx.x;
    const int wid = tid >> 5, lane = tid & 31;
    const int rowBase = blockIdx.x * 128;

    __shared__ float sBias[128];
    if (tid < 128) sBias[tid] = bias[tid];

    const int ar = tid >> 2, ks8 = (tid & 3) << 3;
    const int grow = rowBase + ar;

    float v[8];
    auto loadA = [&](int c) {
        int kg = (c << 5) + ks8;
        if (grow < M) {
            const float* Ap; int kl;
            if (kg < 128) { Ap = A1; kl = kg; } else { Ap = A2; kl = kg - 128; }
            const float4* p = reinterpret_cast<const float4*>(Ap + (size_t)grow * 128 + kl);
            float4 q0 = p[0], q1 = p[1];
            v[0] = q0.x; v[1] = q0.y; v[2] = q0.z; v[3] = q0.w;
            v[4] = q1.x; v[5] = q1.y; v[6] = q1.z; v[7] = q1.w;
        } else {
#pragma unroll
            for (int i = 0; i < 8; i++) v[i] = 0.0f;
        }
    };
    auto storeA = [&](int st) {
        uint32_t hw[4], lw[4];
#pragma unroll
        for (int j = 0; j < 4; j++) {
            float x0 = v[j * 2], x1 = v[j * 2 + 1];
            __nv_bfloat16 h0 = __float2bfloat16_rn(x0);
            __nv_bfloat16 h1 = __float2bfloat16_rn(x1);
            __nv_bfloat16 l0 = __float2bfloat16_rn(x0 - __bfloat162float(h0));
            __nv_bfloat16 l1 = __float2bfloat16_rn(x1 - __bfloat162float(h1));
            hw[j] = (uint32_t)__bfloat16_as_ushort(h0) | ((uint32_t)__bfloat16_as_ushort(h1) << 16);
            lw[j] = (uint32_t)__bfloat16_as_ushort(l0) | ((uint32_t)__bfloat16_as_ushort(l1) << 16);
        }
        char* basep = dsm + st * STGI;
        int off = ar * 80 + ks8 * 2;
        *reinterpret_cast<uint4*>(basep + IAH + off) = make_uint4(hw[0], hw[1], hw[2], hw[3]);
        *reinterpret_cast<uint4*>(basep + IAL + off) = make_uint4(lw[0], lw[1], lw[2], lw[3]);
    };
    auto cpB = [&](int st, int c) {
        int r = tid >> 2, q = tid & 3;
        uint32_t d = sb + st * STGI + r * 80 + (q << 4);
        cp_async16(d + IBH, Bhi + (size_t)r * K + (c << 5) + (q << 3));
        cp_async16(d + IBL, Blo + (size_t)r * K + (c << 5) + (q << 3));
    };

    loadA(0);
    cpB(0, 0);
    storeA(0);
    CP_COMMIT();
    CP_WAIT0();
    __syncthreads();

    const int stripe = wid >> 1, colh = wid & 1;
    wmma::fragment<wmma::accumulator, 16, 16, 16, float> acc[4];
#pragma unroll
    for (int t = 0; t < 4; t++) wmma::fill_fragment(acc[t], 0.0f);

    const int nCh = K >> 5;
    for (int c = 0; c < nCh; c++) {
        const int cur = c & 1;
        const bool more = (c + 1 < nCh);
        if (more) {
            loadA(c + 1);
            cpB(cur ^ 1, c + 1);
            CP_COMMIT();
        }
        const __nv_bfloat16* ah_base = reinterpret_cast<const __nv_bfloat16*>(dsm + cur * STGI + IAH);
        const __nv_bfloat16* al_base = reinterpret_cast<const __nv_bfloat16*>(dsm + cur * STGI + IAL);
        const __nv_bfloat16* bh_base = reinterpret_cast<const __nv_bfloat16*>(dsm + cur * STGI + IBH);
        const __nv_bfloat16* bl_base = reinterpret_cast<const __nv_bfloat16*>(dsm + cur * STGI + IBL);
#pragma unroll
        for (int ks = 0; ks < 32; ks += 16) {
            wmma::fragment<wmma::matrix_a, 16, 16, 16, __nv_bfloat16, wmma::row_major> ah, al;
            wmma::load_matrix_sync(ah, ah_base + stripe * 16 * 40 + ks, 40);
            wmma::load_matrix_sync(al, al_base + stripe * 16 * 40 + ks, 40);
#pragma unroll
            for (int t = 0; t < 4; t++) {
                int brow = colh * 64 + t * 16;
                wmma::fragment<wmma::matrix_b, 16, 16, 16, __nv_bfloat16, wmma::col_major> bh, bl;
                wmma::load_matrix_sync(bh, bh_base + brow * 40 + ks, 40);
                wmma::load_matrix_sync(bl, bl_base + brow * 40 + ks, 40);
                wmma::mma_sync(acc[t], ah, bh, acc[t]);
                wmma::mma_sync(acc[t], ah, bl, acc[t]);
                wmma::mma_sync(acc[t], al, bh, acc[t]);
            }
        }
        if (more) {
            storeA(cur ^ 1);
            CP_WAIT0();
            __syncthreads();
        }
    }

    __syncthreads();
    float* sE = reinterpret_cast<float*>(dsm) + wid * 256;
#pragma unroll
    for (int t = 0; t < 4; t++) {
        int tg = colh * 4 + t;
        wmma::store_matrix_sync(sE, acc[t], 16, wmma::mem_row_major);
        __syncwarp();
#pragma unroll
        for (int i = 0; i < 8; i++) {
            int idx = i * 32 + lane;
            int row = idx >> 4, col = idx & 15;
            int r = rowBase + stripe * 16 + row;
            float vv = gelu_tanh(sE[idx] + sBias[tg * 16 + col]);
            __nv_bfloat16 hh = __float2bfloat16_rn(vv);
            __nv_bfloat16 ll = __float2bfloat16_rn(vv - __bfloat162float(hh));
            size_t o = (size_t)r * 128 + tg * 16 + col;
            Chi[o] = hh;
            Clo[o] = ll;
        }
        __syncwarp();
    }
}

// ---------------- GATv2 edge aggregation (warp per dst node) ----------------
__device__ __forceinline__ float edge_logit(float4 f, float4 fdv, float4 attnv) {
    float4 ev;
    ev.x = f.x + fdv.x; ev.x = (ev.x > 0.f) ? ev.x : 0.2f * ev.x;
    ev.y = f.y + fdv.y; ev.y = (ev.y > 0.f) ? ev.y : 0.2f * ev.y;
    ev.z = f.z + fdv.z; ev.z = (ev.z > 0.f) ? ev.z : 0.2f * ev.z;
    ev.w = f.w + fdv.w; ev.w = (ev.w > 0.f) ? ev.w : 0.2f * ev.w;
    return ev.x * attnv.x + ev.y * attnv.y + ev.z * attnv.z + ev.w * attnv.w;
}

__global__ __launch_bounds__(256) void gat_edge_kernel(
    const float* __restrict__ fs, const float* __restrict__ fd,
    const float* __restrict__ attn, const float* __restrict__ bout,
    const float* __restrict__ bsrc, const float* __restrict__ bdst,
    const int* __restrict__ row_ptr, const int* __restrict__ csr_src,
    __nv_bfloat16* __restrict__ houthi, __nv_bfloat16* __restrict__ houtlo,
    float* __restrict__ houtf, int n_nodes)
{
    const int warp = (blockIdx.x * blockDim.x + threadIdx.x) >> 5;
    const int lane = threadIdx.x & 31;
    if (warp >= n_nodes) return;

    const int off = lane * 4;
    const size_t nodeBase = (size_t)warp * 128;

    const float4 bsv = *reinterpret_cast<const float4*>(bsrc + off);
    const float4 bdv = *reinterpret_cast<const float4*>(bdst + off);
    float4 fdv = *reinterpret_cast<const float4*>(fd + nodeBase + off);
    fdv.x += bsv.x + bdv.x; fdv.y += bsv.y + bdv.y;
    fdv.z += bsv.z + bdv.z; fdv.w += bsv.w + bdv.w;
    const float4 attnv = *reinterpret_cast<const float4*>(attn + off);

    float s = 0.0f;
    float4 acc = make_float4(0.f, 0.f, 0.f, 0.f);

    int e = row_ptr[warp];
    const int end = row_ptr[warp + 1];

    for (; e + 8 <= end; e += 8) {
        float4 f[8];
        float l[8];
#pragma unroll
        for (int j = 0; j < 8; j++) {
            int ij = csr_src[e + j];
            f[j] = *reinterpret_cast<const float4*>(fs + (size_t)ij * 128 + off);
        }
#pragma unroll
        for (int j = 0; j < 8; j++) l[j] = edge_logit(f[j], fdv, attnv);
#pragma unroll
        for (int j = 0; j < 8; j++) l[j] += __shfl_xor_sync(0xffffffffu, l[j], 1);
#pragma unroll
        for (int j = 0; j < 8; j++) l[j] += __shfl_xor_sync(0xffffffffu, l[j], 2);
#pragma unroll
        for (int j = 0; j < 8; j++) l[j] += __shfl_xor_sync(0xffffffffu, l[j], 4);
#pragma unroll
        for (int j = 0; j < 8; j++) {
            float p = __expf(fminf(l[j], 80.f));
            s += p;
            acc.x = fmaf(p, f[j].x, acc.x);
            acc.y = fmaf(p, f[j].y, acc.y);
            acc.z = fmaf(p, f[j].z, acc.z);
            acc.w = fmaf(p, f[j].w, acc.w);
        }
    }
    for (; e + 4 <= end; e += 4) {
        float4 f[4];
        float l[4];
#pragma unroll
        for (int j = 0; j < 4; j++) {
            int ij = csr_src[e + j];
            f[j] = *reinterpret_cast<const float4*>(fs + (size_t)ij * 128 + off);
        }
#pragma unroll
        for (int j = 0; j < 4; j++) l[j] = edge_logit(f[j], fdv, attnv);
#pragma unroll
        for (int j = 0; j < 4; j++) l[j] += __shfl_xor_sync(0xffffffffu, l[j], 1);
#pragma unroll
        for (int j = 0; j < 4; j++) l[j] += __shfl_xor_sync(0xffffffffu, l[j], 2);
#pragma unroll
        for (int j = 0; j < 4; j++) l[j] += __shfl_xor_sync(0xffffffffu, l[j], 4);
#pragma unroll
        for (int j = 0; j < 4; j++) {
            float p = __expf(fminf(l[j], 80.f));
            s += p;
            acc.x = fmaf(p, f[j].x, acc.x);
            acc.y = fmaf(p, f[j].y, acc.y);
            acc.z = fmaf(p, f[j].z, acc.z);
            acc.w = fmaf(p, f[j].w, acc.w);
        }
    }
    for (; e < end; e++) {
        int i0 = csr_src[e];
        float4 f0 = *reinterpret_cast<const float4*>(fs + (size_t)i0 * 128 + off);
        float l0 = edge_logit(f0, fdv, attnv);
        l0 += __shfl_xor_sync(0xffffffffu, l0, 1);
        l0 += __shfl_xor_sync(0xffffffffu, l0, 2);
        l0 += __shfl_xor_sync(0xffffffffu, l0, 4);
        float p0 = __expf(fminf(l0, 80.f));
        s += p0;
        acc.x = fmaf(p0, f0.x, acc.x);
        acc.y = fmaf(p0, f0.y, acc.y);
        acc.z = fmaf(p0, f0.z, acc.z);
        acc.w = fmaf(p0, f0.w, acc.w);
    }

    const float4 bv = *reinterpret_cast<const float4*>(bout + off);
    float inv = 1.0f / (s + 1e-9f);
    float salpha = s * inv;
    float4 o;
    o.x = gelu_tanh(acc.x * inv + bsv.x * salpha + bv.x);
    o.y = gelu_tanh(acc.y * inv + bsv.y * salpha + bv.y);
    o.z = gelu_tanh(acc.z * inv + bsv.z * salpha + bv.z);
    o.w = gelu_tanh(acc.w * inv + bsv.w * salpha + bv.w);

    __nv_bfloat16 h0 = __float2bfloat16_rn(o.x), h1 = __float2bfloat16_rn(o.y);
    __nv_bfloat16 h2 = __float2bfloat16_rn(o.z), h3 = __float2bfloat16_rn(o.w);
    __nv_bfloat16 l0b = __float2bfloat16_rn(o.x - __bfloat162float(h0));
    __nv_bfloat16 l1b = __float2bfloat16_rn(o.y - __bfloat162float(h1));
    __nv_bfloat16 l2b = __float2bfloat16_rn(o.z - __bfloat162float(h2));
    __nv_bfloat16 l3b = __float2bfloat16_rn(o.w - __bfloat162float(h3));
    uint2 hp, lp;
    hp.x = (uint32_t)__bfloat16_as_ushort(h0) | ((uint32_t)__bfloat16_as_ushort(h1) << 16);
    hp.y = (uint32_t)__bfloat16_as_ushort(h2) | ((uint32_t)__bfloat16_as_ushort(h3) << 16);
    lp.x = (uint32_t)__bfloat16_as_ushort(l0b) | ((uint32_t)__bfloat16_as_ushort(l1b) << 16);
    lp.y = (uint32_t)__bfloat16_as_ushort(l2b) | ((uint32_t)__bfloat16_as_ushort(l3b) << 16);
    *reinterpret_cast<uint2*>(houthi + nodeBase + off) = hp;
    *reinterpret_cast<uint2*>(houtlo + nodeBase + off) = lp;
    if (houtf) *reinterpret_cast<float4*>(houtf + nodeBase + off) = o;
}

// ---------------- launch ----------------
extern "C" void kernel_launch(void* const* d_in, const int* in_sizes, int n_in,
                              void* d_out, int out_size) {
    const float* x_t       = (const float*)d_in[0];
    const float* time_emb  = (const float*)d_in[1];
    const int*   src       = (const int*)d_in[2];
    const int*   dst       = (const int*)d_in[3];
    const float* W_init    = (const float*)d_in[4];
    const float* b_init    = (const float*)d_in[5];
    const float* Wsrc_down = (const float*)d_in[6];
    const float* bsrc_down = (const float*)d_in[7];
    const float* Wdst_down = (const float*)d_in[8];
    const float* bdst_down = (const float*)d_in[9];
    const float* attn_down = (const float*)d_in[10];
    const float* bout_down = (const float*)d_in[11];
    const float* Wsrc_mid  = (const float*)d_in[12];
    const float* bsrc_mid  = (const float*)d_in[13];
    const float* Wdst_mid  = (const float*)d_in[14];
    const float* bdst_mid  = (const float*)d_in[15];
    const float* attn_mid  = (const float*)d_in[16];
    const float* bout_mid  = (const float*)d_in[17];
    const float* Wsrc_up   = (const float*)d_in[18];
    const float* bsrc_up   = (const float*)d_in[19];
    const float* Wdst_up   = (const float*)d_in[20];
    const float* bdst_up   = (const float*)d_in[21];
    const float* attn_up   = (const float*)d_in[22];
    const float* bout_up   = (const float*)d_in[23];
    const float* W_fin     = (const float*)d_in[24];
    const float* b_fin     = (const float*)d_in[25];

    const int Nn = in_sizes[0] / HID;
    const int E  = in_sizes[2];

    void* pf; cudaGetSymbolAddress(&pf, g_buf);
    void* pi; cudaGetSymbolAddress(&pi, g_ibuf);
    void* pwh; cudaGetSymbolAddress(&pwh, g_whi);
    void* pwl; cudaGetSymbolAddress(&pwl, g_wlo);
    float* base = (float*)pf;
    const size_t SL = (size_t)NPAD * HID;
    float* fs = base + 0 * SL;
    float* fd = base + 1 * SL;
    __nv_bfloat16* hb = (__nv_bfloat16*)(base + 2 * SL);
    const size_t HS = (size_t)NPAD * HID;
    auto Hhi = [&](int i) { return hb + (size_t)i * 2 * HS; };
    auto Hlo = [&](int i) { return hb + (size_t)i * 2 * HS + HS; };

    int* ib = (int*)pi;
    int* deg     = ib;
    int* row_ptr = deg + NN;
    int* cur     = row_ptr + NN + 1;
    int* csr     = cur + NN;
    int* part    = csr + EE;
    __nv_bfloat16* whi = (__nv_bfloat16*)pwh;
    __nv_bfloat16* wlo = (__nv_bfloat16*)pwl;

    float* out = (float*)d_out;
    float* houtf_fin = (out_size >= 2 * Nn * HID) ? (out + (size_t)Nn * HID)
                                                  : (float*)Hhi(2);

    cudaFuncSetAttribute(tgemm_fast<1>, cudaFuncAttributeMaxDynamicSharedMemorySize, TGF_DSM);
    cudaFuncSetAttribute(tgemm_fast<2>, cudaFuncAttributeMaxDynamicSharedMemorySize, TGF_DSM);
    cudaFuncSetAttribute(tgemm_init, cudaFuncAttributeMaxDynamicSharedMemorySize, TGI_DSM);

    dim3 tb(256);
    dim3 tg(512);
    int gE = (E + 255) / 256;
    int gx = (Nn + 127) / 128;
    int gGat = (Nn * 32 + 255) / 256;
    int nBlk = (Nn + 1023) / 1024;

    // ---- ONE side stream (same footprint as the passing R11 config).
    // It runs bulk wconv FIRST (joined before the first hot GEMM), then the
    // CSR chain (joined before the first edge kernel).
    cudaStream_t sSide;
    cudaStreamCreateWithFlags(&sSide, cudaStreamNonBlocking);
    cudaEvent_t evFork, evWc, evCsr;
    cudaEventCreateWithFlags(&evFork, cudaEventDisableTiming);
    cudaEventCreateWithFlags(&evWc, cudaEventDisableTiming);
    cudaEventCreateWithFlags(&evCsr, cudaEventDisableTiming);

    cudaEventRecord(evFork, 0);
    cudaStreamWaitEvent(sSide, evFork, 0);

    // bulk weight conversion (everything after the init-GEMM slice)
    wconv_kernel<<<(WTOT - 32768 + 255) / 256, tb, 0, sSide>>>(
        W_init, Wsrc_down, Wdst_down, Wsrc_mid, Wdst_mid, Wsrc_up, Wdst_up, W_fin,
        whi, wlo, 32768, WTOT);
    cudaEventRecord(evWc, sSide);

    // CSR build
    cudaMemsetAsync(deg, 0, sizeof(int) * Nn, sSide);
    hist_kernel<<<gE, tb, 0, sSide>>>(dst, deg, E);
    scan_part_kernel<<<nBlk, 1024, 0, sSide>>>(deg, part, Nn);
    scan_off_kernel<<<1, 32, 0, sSide>>>(part, nBlk);
    scan_final_kernel<<<nBlk, 1024, 0, sSide>>>(deg, part, row_ptr, cur, Nn);
    scatter_kernel<<<gE, tb, 0, sSide>>>(src, dst, cur, csr, E);
    cudaEventRecord(evCsr, sSide);

    const int OG_INIT = 0, OG_D0 = 32768, OG_D1 = 65536, OG_MID = 98304,
              OG_U0 = 131072, OG_U1 = 196608, OG_FIN = 262144;

    // ---- main stream: init-slice wconv + init GEMM ----
    wconv_kernel<<<(32768 + 255) / 256, tb>>>(
        W_init, Wsrc_down, Wdst_down, Wsrc_mid, Wdst_mid, Wsrc_up, Wdst_up, W_fin,
        whi, wlo, 0, 32768);

    tgemm_init<<<gx, tg, TGI_DSM>>>(x_t, time_emb, whi + OG_INIT, wlo + OG_INIT,
                                    b_init, Hhi(0), Hlo(0), Nn);

    // join bulk wconv before first hot GEMM (needs OG_D0 weights)
    cudaStreamWaitEvent(0, evWc, 0);

    tgemm_fast<2><<<gx, tg, TGF_DSM>>>(Hhi(0), Hlo(0), nullptr, nullptr,
                                       whi + OG_D0, wlo + OG_D0, nullptr, fs, fd, Nn, 128);

    // join CSR before first edge kernel
    cudaStreamWaitEvent(0, evCsr, 0);

    gat_edge_kernel<<<gGat, tb>>>(fs, fd, attn_down, bout_down, bsrc_down, bdst_down,
                                  row_ptr, csr, Hhi(1), Hlo(1), nullptr, Nn);

    tgemm_fast<2><<<gx, tg, TGF_DSM>>>(Hhi(1), Hlo(1), nullptr, nullptr,
                                       whi + OG_D1, wlo + OG_D1, nullptr, fs, fd, Nn, 128);
    gat_edge_kernel<<<gGat, tb>>>(fs, fd, attn_down + HID, bout_down + HID,
                                  bsrc_down + HID, bdst_down + HID, row_ptr, csr,
                                  Hhi(2), Hlo(2), nullptr, Nn);

    tgemm_fast<2><<<gx, tg, TGF_DSM>>>(Hhi(2), Hlo(2), nullptr, nullptr,
                                       whi + OG_MID, wlo + OG_MID, nullptr, fs, fd, Nn, 128);
    gat_edge_kernel<<<gGat, tb>>>(fs, fd, attn_mid, bout_mid, bsrc_mid, bdst_mid,
                                  row_ptr, csr, Hhi(3), Hlo(3), nullptr, Nn);

    tgemm_fast<2><<<gx, tg, TGF_DSM>>>(Hhi(3), Hlo(3), Hhi(1), Hlo(1),
                                       whi + OG_U0, wlo + OG_U0, nullptr, fs, fd, Nn, 256);
    gat_edge_kernel<<<gGat, tb>>>(fs, fd, attn_up, bout_up, bsrc_up, bdst_up,
                                  row_ptr, csr, Hhi(4), Hlo(4), nullptr, Nn);

    tgemm_fast<2><<<gx, tg, TGF_DSM>>>(Hhi(4), Hlo(4), Hhi(0), Hlo(0),
                                       whi + OG_U1, wlo + OG_U1, nullptr, fs, fd, Nn, 256);
    gat_edge_kernel<<<gGat, tb>>>(fs, fd, attn_up + HID, bout_up + HID,
                                  bsrc_up + HID, bdst_up + HID, row_ptr, csr,
                                  Hhi(5), Hlo(5), houtf_fin, Nn);

    tgemm_fast<1><<<gx, tg, TGF_DSM>>>(Hhi(5), Hlo(5), nullptr, nullptr,
                                       whi + OG_FIN, wlo + OG_FIN, b_fin,
                                       out, nullptr, Nn, 128);
    if (houtf_fin != out + (size_t)Nn * HID && out_size >= 2 * Nn * HID) {
        cudaMemcpyAsync(out + (size_t)Nn * HID, houtf_fin,
                        (size_t)Nn * HID * sizeof(float), cudaMemcpyDeviceToDevice);
    }
}

// round 16
// speedup vs baseline: 1.0002x; 1.0002x over previous
#include <cuda_runtime.h>
#include <cuda_bf16.h>
#include <mma.h>
#include <math.h>
#include <stdint.h>

using namespace nvcuda;

#define NN 50000
#define NPAD 50048
#define EE 800000
#define HID 128

// ---------------- scratch (no allocation allowed) ----------------
__device__ float g_buf[(size_t)8 * NPAD * HID];
__device__ int g_ibuf[NN + (NN + 1) + NN + EE + 64];
#define WTOT 278528
__device__ __align__(16) __nv_bfloat16 g_whi[WTOT];
__device__ __align__(16) __nv_bfloat16 g_wlo[WTOT];

__device__ __forceinline__ float gelu_tanh(float x) {
    float x3 = x * x * x;
    float t = tanhf(0.7978845608028654f * (x + 0.044715f * x3));
    return 0.5f * x * (1.0f + t);
}

__device__ __forceinline__ uint32_t smem_u32(const void* p) {
    uint32_t a;
    asm("{ .reg .u64 t; cvta.to.shared.u64 t, %1; cvt.u32.u64 %0, t; }" : "=r"(a) : "l"(p));
    return a;
}
__device__ __forceinline__ void cp_async16(uint32_t dst, const void* src) {
    asm volatile("cp.async.cg.shared.global [%0], [%1], 16;" :: "r"(dst), "l"(src));
}
#define CP_COMMIT() asm volatile("cp.async.commit_group;" ::: "memory")
#define CP_WAIT0()  asm volatile("cp.async.wait_group 0;" ::: "memory")
#define CP_WAIT1()  asm volatile("cp.async.wait_group 1;" ::: "memory")

// ---------------- CSR build ----------------
__global__ void hist_kernel(const int* __restrict__ dst, int* __restrict__ deg, int E) {
    int e = blockIdx.x * blockDim.x + threadIdx.x;
    if (e < E) atomicAdd(&deg[dst[e]], 1);
}

__global__ void scan_part_kernel(const int* __restrict__ deg, int* __restrict__ part, int n) {
    __shared__ int ws[32];
    const int lane = threadIdx.x & 31, wid = threadIdx.x >> 5;
    int i = blockIdx.x * 1024 + threadIdx.x;
    int v = (i < n) ? deg[i] : 0;
#pragma unroll
    for (int o = 16; o; o >>= 1) v += __shfl_xor_sync(0xffffffffu, v, o);
    if (lane == 0) ws[wid] = v;
    __syncthreads();
    if (wid == 0) {
        int x = ws[lane];
#pragma unroll
        for (int o = 16; o; o >>= 1) x += __shfl_xor_sync(0xffffffffu, x, o);
        if (lane == 0) part[blockIdx.x] = x;
    }
}

__global__ void scan_off_kernel(int* __restrict__ part, int nb) {
    int lane = threadIdx.x;
    int v0 = (2 * lane < nb) ? part[2 * lane] : 0;
    int v1 = (2 * lane + 1 < nb) ? part[2 * lane + 1] : 0;
    int sum = v0 + v1;
    int x = sum;
#pragma unroll
    for (int o = 1; o < 32; o <<= 1) {
        int t = __shfl_up_sync(0xffffffffu, x, o);
        if (lane >= o) x += t;
    }
    int excl = x - sum;
    if (2 * lane < nb) part[2 * lane] = excl;
    if (2 * lane + 1 < nb) part[2 * lane + 1] = excl + v0;
}

__global__ void scan_final_kernel(const int* __restrict__ deg, const int* __restrict__ part,
                                  int* __restrict__ row_ptr, int* __restrict__ cur, int n) {
    __shared__ int wsum[32];
    const int lane = threadIdx.x & 31, wid = threadIdx.x >> 5;
    int i = blockIdx.x * 1024 + threadIdx.x;
    int v = (i < n) ? deg[i] : 0;
    int x = v;
#pragma unroll
    for (int o = 1; o < 32; o <<= 1) {
        int t = __shfl_up_sync(0xffffffffu, x, o);
        if (lane >= o) x += t;
    }
    if (lane == 31) wsum[wid] = x;
    __syncthreads();
    if (wid == 0) {
        int y = wsum[lane];
#pragma unroll
        for (int o = 1; o < 32; o <<= 1) {
            int t = __shfl_up_sync(0xffffffffu, y, o);
            if (lane >= o) y += t;
        }
        wsum[lane] = y;
    }
    __syncthreads();
    int off = part[blockIdx.x] + (wid > 0 ? wsum[wid - 1] : 0);
    if (i < n) {
        row_ptr[i + 1] = off + x;
        cur[i] = off + x - v;
    }
    if (i == 0) row_ptr[0] = 0;
}

__global__ void scatter_kernel(const int* __restrict__ src, const int* __restrict__ dst,
                               int* __restrict__ cur, int* __restrict__ csr_src, int E) {
    int e = blockIdx.x * blockDim.x + threadIdx.x;
    if (e < E) {
        int p = atomicAdd(&cur[dst[e]], 1);
        csr_src[p] = src[e];
    }
}

// ---------------- weight transpose + bf16 split ----------------
__global__ void wconv_kernel(
    const float* __restrict__ Wi,
    const float* __restrict__ Wsd, const float* __restrict__ Wdd,
    const float* __restrict__ Wsm, const float* __restrict__ Wdm,
    const float* __restrict__ Wsu, const float* __restrict__ Wdu,
    const float* __restrict__ Wf,
    __nv_bfloat16* __restrict__ bhi, __nv_bfloat16* __restrict__ blo)
{
    int idx = blockIdx.x * blockDim.x + threadIdx.x;
    if (idx >= WTOT) return;
    int base, K; const float *S, *D2;
    if (idx < 32768)       { base = 0;      K = 256; S = Wi;           D2 = nullptr; }
    else if (idx < 65536)  { base = 32768;  K = 128; S = Wsd;          D2 = Wdd; }
    else if (idx < 98304)  { base = 65536;  K = 128; S = Wsd + 16384;  D2 = Wdd + 16384; }
    else if (idx < 131072) { base = 98304;  K = 128; S = Wsm;          D2 = Wdm; }
    else if (idx < 196608) { base = 131072; K = 256; S = Wsu;          D2 = Wdu; }
    else if (idx < 262144) { base = 196608; K = 256; S = Wsu + 32768;  D2 = Wdu + 32768; }
    else                   { base = 262144; K = 128; S = Wf;           D2 = nullptr; }
    int local = idx - base;
    int n = local / K, k = local - n * K;
    const float* W = (D2 && n >= 128) ? D2 : S;
    int nc = (D2 && n >= 128) ? n - 128 : n;
    float x = W[(size_t)k * 128 + nc];
    __nv_bfloat16 h = __float2bfloat16_rn(x);
    bhi[idx] = h;
    blo[idx] = __float2bfloat16_rn(x - __bfloat162float(h));
}

// ================= tgemm_fast: A bf16 hi/lo, full cp.async, 3-stage =========
#define STG 61440
#define SAH 0
#define SAL 10240
#define SBH 20480
#define SBL 40960
#define TGF_DSM (3 * STG)

template<int NB>
__global__ __launch_bounds__(512) void tgemm_fast(
    const __nv_bfloat16* __restrict__ Ahi1, const __nv_bfloat16* __restrict__ Alo1,
    const __nv_bfloat16* __restrict__ Ahi2, const __nv_bfloat16* __restrict__ Alo2,
    const __nv_bfloat16* __restrict__ Bhi, const __nv_bfloat16* __restrict__ Blo,
    const float* __restrict__ bias,
    float* __restrict__ Ca, float* __restrict__ Cb,
    int M, int K)
{
    extern __shared__ char dsm[];
    const uint32_t sb = smem_u32(dsm);
    const int tid = threadIdx.x;
    const int wid = tid >> 5, lane = tid & 31;
    const int rowBase = blockIdx.x * 128;

    __shared__ float sBias[128];
    if (NB == 1 && tid < 128) sBias[tid] = bias[tid];

    auto cpAll = [&](int st, int c) {
        {
            const __nv_bfloat16* Ah = (c < 4) ? Ahi1 : Ahi2;
            const __nv_bfloat16* Al = (c < 4) ? Alo1 : Alo2;
            int cc = c & 3;
            int r = tid >> 2, q = tid & 3;
            size_t so = (size_t)(rowBase + r) * 128 + cc * 32 + q * 8;
            uint32_t d = sb + st * STG + r * 80 + (q << 4);
            cp_async16(d + SAH, Ah + so);
            cp_async16(d + SAL, Al + so);
        }
        if (NB == 2) {
            int r = tid >> 1, q0 = (tid & 1) << 1;
#pragma unroll
            for (int dq = 0; dq < 2; dq++) {
                int q = q0 + dq;
                uint32_t d = sb + st * STG + r * 80 + (q << 4);
                cp_async16(d + SBH, Bhi + (size_t)r * K + (c << 5) + (q << 3));
                cp_async16(d + SBL, Blo + (size_t)r * K + (c << 5) + (q << 3));
            }
        } else {
            int r = tid >> 2, q = tid & 3;
            uint32_t d = sb + st * STG + r * 80 + (q << 4);
            cp_async16(d + SBH, Bhi + (size_t)r * K + (c << 5) + (q << 3));
            cp_async16(d + SBL, Blo + (size_t)r * K + (c << 5) + (q << 3));
        }
    };

    const int nCh = K >> 5;

    cpAll(0, 0); CP_COMMIT();
    if (nCh > 1) { cpAll(1, 1); CP_COMMIT(); }

    if (NB == 2) {
        const int rowg = wid & 3;
        const int colh = (wid >> 2) & 1;
        const int hb   = wid >> 3;
        wmma::fragment<wmma::accumulator, 16, 16, 16, float> acc[8];
#pragma unroll
        for (int t = 0; t < 8; t++) wmma::fill_fragment(acc[t], 0.0f);

        for (int c = 0; c < nCh; c++) {
            if (c + 1 == nCh) { CP_WAIT0(); } else { CP_WAIT1(); }
            __syncthreads();
            const int st = c % 3;
            const __nv_bfloat16* ah_base = reinterpret_cast<const __nv_bfloat16*>(dsm + st * STG + SAH);
            const __nv_bfloat16* al_base = reinterpret_cast<const __nv_bfloat16*>(dsm + st * STG + SAL);
            const __nv_bfloat16* bh_base = reinterpret_cast<const __nv_bfloat16*>(dsm + st * STG + SBH);
            const __nv_bfloat16* bl_base = reinterpret_cast<const __nv_bfloat16*>(dsm + st * STG + SBL);
#pragma unroll
            for (int ks = 0; ks < 32; ks += 16) {
                wmma::fragment<wmma::matrix_a, 16, 16, 16, __nv_bfloat16, wmma::row_major> ah0, ah1, al0, al1;
                wmma::load_matrix_sync(ah0, ah_base + (rowg * 32) * 40 + ks, 40);
                wmma::load_matrix_sync(ah1, ah_base + (rowg * 32 + 16) * 40 + ks, 40);
                wmma::load_matrix_sync(al0, al_base + (rowg * 32) * 40 + ks, 40);
                wmma::load_matrix_sync(al1, al_base + (rowg * 32 + 16) * 40 + ks, 40);
#pragma unroll
                for (int t = 0; t < 4; t++) {
                    int brow = hb * 128 + colh * 64 + t * 16;
                    wmma::fragment<wmma::matrix_b, 16, 16, 16, __nv_bfloat16, wmma::col_major> bh, bl;
                    wmma::load_matrix_sync(bh, bh_base + brow * 40 + ks, 40);
                    wmma::load_matrix_sync(bl, bl_base + brow * 40 + ks, 40);
                    wmma::mma_sync(acc[t], ah0, bh, acc[t]);
                    wmma::mma_sync(acc[t], ah0, bl, acc[t]);
                    wmma::mma_sync(acc[t], al0, bh, acc[t]);
                    wmma::mma_sync(acc[4 + t], ah1, bh, acc[4 + t]);
                    wmma::mma_sync(acc[4 + t], ah1, bl, acc[4 + t]);
                    wmma::mma_sync(acc[4 + t], al1, bh, acc[4 + t]);
                }
            }
            if (c + 2 < nCh) { cpAll((c + 2) % 3, c + 2); CP_COMMIT(); }
        }
        float* Cp = hb ? Cb : Ca;
#pragma unroll
        for (int s = 0; s < 2; s++) {
#pragma unroll
            for (int t = 0; t < 4; t++) {
                wmma::store_matrix_sync(
                    Cp + (size_t)(rowBase + rowg * 32 + s * 16) * 128 + colh * 64 + t * 16,
                    acc[s * 4 + t], 128, wmma::mem_row_major);
            }
        }
    } else {
        const int stripe = wid >> 1, colh = wid & 1;
        wmma::fragment<wmma::accumulator, 16, 16, 16, float> acc[4];
#pragma unroll
        for (int t = 0; t < 4; t++) wmma::fill_fragment(acc[t], 0.0f);

        for (int c = 0; c < nCh; c++) {
            if (c + 1 == nCh) { CP_WAIT0(); } else { CP_WAIT1(); }
            __syncthreads();
            const int st = c % 3;
            const __nv_bfloat16* ah_base = reinterpret_cast<const __nv_bfloat16*>(dsm + st * STG + SAH);
            const __nv_bfloat16* al_base = reinterpret_cast<const __nv_bfloat16*>(dsm + st * STG + SAL);
            const __nv_bfloat16* bh_base = reinterpret_cast<const __nv_bfloat16*>(dsm + st * STG + SBH);
            const __nv_bfloat16* bl_base = reinterpret_cast<const __nv_bfloat16*>(dsm + st * STG + SBL);
#pragma unroll
            for (int ks = 0; ks < 32; ks += 16) {
                wmma::fragment<wmma::matrix_a, 16, 16, 16, __nv_bfloat16, wmma::row_major> ah, al;
                wmma::load_matrix_sync(ah, ah_base + stripe * 16 * 40 + ks, 40);
                wmma::load_matrix_sync(al, al_base + stripe * 16 * 40 + ks, 40);
#pragma unroll
                for (int t = 0; t < 4; t++) {
                    int brow = colh * 64 + t * 16;
                    wmma::fragment<wmma::matrix_b, 16, 16, 16, __nv_bfloat16, wmma::col_major> bh, bl;
                    wmma::load_matrix_sync(bh, bh_base + brow * 40 + ks, 40);
                    wmma::load_matrix_sync(bl, bl_base + brow * 40 + ks, 40);
                    wmma::mma_sync(acc[t], ah, bh, acc[t]);
                    wmma::mma_sync(acc[t], ah, bl, acc[t]);
                    wmma::mma_sync(acc[t], al, bh, acc[t]);
                }
            }
            if (c + 2 < nCh) { cpAll((c + 2) % 3, c + 2); CP_COMMIT(); }
        }

        __syncthreads();
        float* sE = reinterpret_cast<float*>(dsm) + wid * 256;
#pragma unroll
        for (int t = 0; t < 4; t++) {
            int tg = colh * 4 + t;
            wmma::store_matrix_sync(sE, acc[t], 16, wmma::mem_row_major);
            __syncwarp();
#pragma unroll
            for (int i = 0; i < 8; i++) {
                int idx = i * 32 + lane;
                int row = idx >> 4, col = idx & 15;
                int r = rowBase + stripe * 16 + row;
                if (r < M) {
                    float vv = sE[idx] + sBias[tg * 16 + col];
                    Ca[(size_t)r * 128 + tg * 16 + col] = vv;
                }
            }
            __syncwarp();
        }
    }
}

// ================= tgemm_init: A fp32 (x_t | time_emb), out bf16 pair + gelu
#define STGI 40960
#define IAH 0
#define IAL 10240
#define IBH 20480
#define IBL 30720
#define TGI_DSM (2 * STGI)

__global__ __launch_bounds__(512) void tgemm_init(
    const float* __restrict__ A1, const float* __restrict__ A2,
    const __nv_bfloat16* __restrict__ Bhi, const __nv_bfloat16* __restrict__ Blo,
    const float* __restrict__ bias,
    __nv_bfloat16* __restrict__ Chi, __nv_bfloat16* __restrict__ Clo,
    int M)
{
    const int K = 256;
    extern __shared__ char dsm[];
    const uint32_t sb = smem_u32(dsm);
    const int tid = threadIdx.x;
    const int wid = tid >> 5, lane = tid & 31;
    const int rowBase = blockIdx.x * 128;

    __shared__ float sBias[128];
    if (tid < 128) sBias[tid] = bias[tid];

    const int ar = tid >> 2, ks8 = (tid & 3) << 3;
    const int grow = rowBase + ar;

    float v[8];
    auto loadA = [&](int c) {
        int kg = (c << 5) + ks8;
        if (grow < M) {
            const float* Ap; int kl;
            if (kg < 128) { Ap = A1; kl = kg; } else { Ap = A2; kl = kg - 128; }
            const float4* p = reinterpret_cast<const float4*>(Ap + (size_t)grow * 128 + kl);
            float4 q0 = p[0], q1 = p[1];
            v[0] = q0.x; v[1] = q0.y; v[2] = q0.z; v[3] = q0.w;
            v[4] = q1.x; v[5] = q1.y; v[6] = q1.z; v[7] = q1.w;
        } else {
#pragma unroll
            for (int i = 0; i < 8; i++) v[i] = 0.0f;
        }
    };
    auto storeA = [&](int st) {
        uint32_t hw[4], lw[4];
#pragma unroll
        for (int j = 0; j < 4; j++) {
            float x0 = v[j * 2], x1 = v[j * 2 + 1];
            __nv_bfloat16 h0 = __float2bfloat16_rn(x0);
            __nv_bfloat16 h1 = __float2bfloat16_rn(x1);
            __nv_bfloat16 l0 = __float2bfloat16_rn(x0 - __bfloat162float(h0));
            __nv_bfloat16 l1 = __float2bfloat16_rn(x1 - __bfloat162float(h1));
            hw[j] = (uint32_t)__bfloat16_as_ushort(h0) | ((uint32_t)__bfloat16_as_ushort(h1) << 16);
            lw[j] = (uint32_t)__bfloat16_as_ushort(l0) | ((uint32_t)__bfloat16_as_ushort(l1) << 16);
        }
        char* basep = dsm + st * STGI;
        int off = ar * 80 + ks8 * 2;
        *reinterpret_cast<uint4*>(basep + IAH + off) = make_uint4(hw[0], hw[1], hw[2], hw[3]);
        *reinterpret_cast<uint4*>(basep + IAL + off) = make_uint4(lw[0], lw[1], lw[2], lw[3]);
    };
    auto cpB = [&](int st, int c) {
        int r = tid >> 2, q = tid & 3;
        uint32_t d = sb + st * STGI + r * 80 + (q << 4);
        cp_async16(d + IBH, Bhi + (size_t)r * K + (c << 5) + (q << 3));
        cp_async16(d + IBL, Blo + (size_t)r * K + (c << 5) + (q << 3));
    };

    loadA(0);
    cpB(0, 0);
    storeA(0);
    CP_COMMIT();
    CP_WAIT0();
    __syncthreads();

    const int stripe = wid >> 1, colh = wid & 1;
    wmma::fragment<wmma::accumulator, 16, 16, 16, float> acc[4];
#pragma unroll
    for (int t = 0; t < 4; t++) wmma::fill_fragment(acc[t], 0.0f);

    const int nCh = K >> 5;
    for (int c = 0; c < nCh; c++) {
        const int cur = c & 1;
        const bool more = (c + 1 < nCh);
        if (more) {
            loadA(c + 1);
            cpB(cur ^ 1, c + 1);
            CP_COMMIT();
        }
        const __nv_bfloat16* ah_base = reinterpret_cast<const __nv_bfloat16*>(dsm + cur * STGI + IAH);
        const __nv_bfloat16* al_base = reinterpret_cast<const __nv_bfloat16*>(dsm + cur * STGI + IAL);
        const __nv_bfloat16* bh_base = reinterpret_cast<const __nv_bfloat16*>(dsm + cur * STGI + IBH);
        const __nv_bfloat16* bl_base = reinterpret_cast<const __nv_bfloat16*>(dsm + cur * STGI + IBL);
#pragma unroll
        for (int ks = 0; ks < 32; ks += 16) {
            wmma::fragment<wmma::matrix_a, 16, 16, 16, __nv_bfloat16, wmma::row_major> ah, al;
            wmma::load_matrix_sync(ah, ah_base + stripe * 16 * 40 + ks, 40);
            wmma::load_matrix_sync(al, al_base + stripe * 16 * 40 + ks, 40);
#pragma unroll
            for (int t = 0; t < 4; t++) {
                int brow = colh * 64 + t * 16;
                wmma::fragment<wmma::matrix_b, 16, 16, 16, __nv_bfloat16, wmma::col_major> bh, bl;
                wmma::load_matrix_sync(bh, bh_base + brow * 40 + ks, 40);
                wmma::load_matrix_sync(bl, bl_base + brow * 40 + ks, 40);
                wmma::mma_sync(acc[t], ah, bh, acc[t]);
                wmma::mma_sync(acc[t], ah, bl, acc[t]);
                wmma::mma_sync(acc[t], al, bh, acc[t]);
            }
        }
        if (more) {
            storeA(cur ^ 1);
            CP_WAIT0();
            __syncthreads();
        }
    }

    __syncthreads();
    float* sE = reinterpret_cast<float*>(dsm) + wid * 256;
#pragma unroll
    for (int t = 0; t < 4; t++) {
        int tg = colh * 4 + t;
        wmma::store_matrix_sync(sE, acc[t], 16, wmma::mem_row_major);
        __syncwarp();
#pragma unroll
        for (int i = 0; i < 8; i++) {
            int idx = i * 32 + lane;
            int row = idx >> 4, col = idx & 15;
            int r = rowBase + stripe * 16 + row;
            float vv = gelu_tanh(sE[idx] + sBias[tg * 16 + col]);
            __nv_bfloat16 hh = __float2bfloat16_rn(vv);
            __nv_bfloat16 ll = __float2bfloat16_rn(vv - __bfloat162float(hh));
            size_t o = (size_t)r * 128 + tg * 16 + col;
            Chi[o] = hh;
            Clo[o] = ll;
        }
        __syncwarp();
    }
}

// ---------------- GATv2 edge aggregation (warp per dst node) ----------------
__device__ __forceinline__ float edge_logit(float4 f, float4 fdv, float4 attnv) {
    float4 ev;
    ev.x = f.x + fdv.x; ev.x = (ev.x > 0.f) ? ev.x : 0.2f * ev.x;
    ev.y = f.y + fdv.y; ev.y = (ev.y > 0.f) ? ev.y : 0.2f * ev.y;
    ev.z = f.z + fdv.z; ev.z = (ev.z > 0.f) ? ev.z : 0.2f * ev.z;
    ev.w = f.w + fdv.w; ev.w = (ev.w > 0.f) ? ev.w : 0.2f * ev.w;
    return ev.x * attnv.x + ev.y * attnv.y + ev.z * attnv.z + ev.w * attnv.w;
}

__global__ __launch_bounds__(256) void gat_edge_kernel(
    const float* __restrict__ fs, const float* __restrict__ fd,
    const float* __restrict__ attn, const float* __restrict__ bout,
    const float* __restrict__ bsrc, const float* __restrict__ bdst,
    const int* __restrict__ row_ptr, const int* __restrict__ csr_src,
    __nv_bfloat16* __restrict__ houthi, __nv_bfloat16* __restrict__ houtlo,
    float* __restrict__ houtf, int n_nodes)
{
    const int warp = (blockIdx.x * blockDim.x + threadIdx.x) >> 5;
    const int lane = threadIdx.x & 31;
    if (warp >= n_nodes) return;

    const int off = lane * 4;
    const size_t nodeBase = (size_t)warp * 128;

    const float4 bsv = *reinterpret_cast<const float4*>(bsrc + off);
    const float4 bdv = *reinterpret_cast<const float4*>(bdst + off);
    float4 fdv = *reinterpret_cast<const float4*>(fd + nodeBase + off);
    fdv.x += bsv.x + bdv.x; fdv.y += bsv.y + bdv.y;
    fdv.z += bsv.z + bdv.z; fdv.w += bsv.w + bdv.w;
    const float4 attnv = *reinterpret_cast<const float4*>(attn + off);

    float s = 0.0f;
    float4 acc = make_float4(0.f, 0.f, 0.f, 0.f);

    int e = row_ptr[warp];
    const int end = row_ptr[warp + 1];

    for (; e + 8 <= end; e += 8) {
        float4 f[8];
        float l[8];
#pragma unroll
        for (int j = 0; j < 8; j++) {
            int ij = csr_src[e + j];
            f[j] = *reinterpret_cast<const float4*>(fs + (size_t)ij * 128 + off);
        }
#pragma unroll
        for (int j = 0; j < 8; j++) l[j] = edge_logit(f[j], fdv, attnv);
#pragma unroll
        for (int j = 0; j < 8; j++) l[j] += __shfl_xor_sync(0xffffffffu, l[j], 1);
#pragma unroll
        for (int j = 0; j < 8; j++) l[j] += __shfl_xor_sync(0xffffffffu, l[j], 2);
#pragma unroll
        for (int j = 0; j < 8; j++) l[j] += __shfl_xor_sync(0xffffffffu, l[j], 4);
#pragma unroll
        for (int j = 0; j < 8; j++) {
            float p = __expf(fminf(l[j], 80.f));
            s += p;
            acc.x = fmaf(p, f[j].x, acc.x);
            acc.y = fmaf(p, f[j].y, acc.y);
            acc.z = fmaf(p, f[j].z, acc.z);
            acc.w = fmaf(p, f[j].w, acc.w);
        }
    }
    for (; e + 4 <= end; e += 4) {
        float4 f[4];
        float l[4];
#pragma unroll
        for (int j = 0; j < 4; j++) {
            int ij = csr_src[e + j];
            f[j] = *reinterpret_cast<const float4*>(fs + (size_t)ij * 128 + off);
        }
#pragma unroll
        for (int j = 0; j < 4; j++) l[j] = edge_logit(f[j], fdv, attnv);
#pragma unroll
        for (int j = 0; j < 4; j++) l[j] += __shfl_xor_sync(0xffffffffu, l[j], 1);
#pragma unroll
        for (int j = 0; j < 4; j++) l[j] += __shfl_xor_sync(0xffffffffu, l[j], 2);
#pragma unroll
        for (int j = 0; j < 4; j++) l[j] += __shfl_xor_sync(0xffffffffu, l[j], 4);
#pragma unroll
        for (int j = 0; j < 4; j++) {
            float p = __expf(fminf(l[j], 80.f));
            s += p;
            acc.x = fmaf(p, f[j].x, acc.x);
            acc.y = fmaf(p, f[j].y, acc.y);
            acc.z = fmaf(p, f[j].z, acc.z);
            acc.w = fmaf(p, f[j].w, acc.w);
        }
    }
    for (; e < end; e++) {
        int i0 = csr_src[e];
        float4 f0 = *reinterpret_cast<const float4*>(fs + (size_t)i0 * 128 + off);
        float l0 = edge_logit(f0, fdv, attnv);
        l0 += __shfl_xor_sync(0xffffffffu, l0, 1);
        l0 += __shfl_xor_sync(0xffffffffu, l0, 2);
        l0 += __shfl_xor_sync(0xffffffffu, l0, 4);
        float p0 = __expf(fminf(l0, 80.f));
        s += p0;
        acc.x = fmaf(p0, f0.x, acc.x);
        acc.y = fmaf(p0, f0.y, acc.y);
        acc.z = fmaf(p0, f0.z, acc.z);
        acc.w = fmaf(p0, f0.w, acc.w);
    }

    const float4 bv = *reinterpret_cast<const float4*>(bout + off);
    float inv = 1.0f / (s + 1e-9f);
    float salpha = s * inv;
    float4 o;
    o.x = gelu_tanh(acc.x * inv + bsv.x * salpha + bv.x);
    o.y = gelu_tanh(acc.y * inv + bsv.y * salpha + bv.y);
    o.z = gelu_tanh(acc.z * inv + bsv.z * salpha + bv.z);
    o.w = gelu_tanh(acc.w * inv + bsv.w * salpha + bv.w);

    __nv_bfloat16 h0 = __float2bfloat16_rn(o.x), h1 = __float2bfloat16_rn(o.y);
    __nv_bfloat16 h2 = __float2bfloat16_rn(o.z), h3 = __float2bfloat16_rn(o.w);
    __nv_bfloat16 l0b = __float2bfloat16_rn(o.x - __bfloat162float(h0));
    __nv_bfloat16 l1b = __float2bfloat16_rn(o.y - __bfloat162float(h1));
    __nv_bfloat16 l2b = __float2bfloat16_rn(o.z - __bfloat162float(h2));
    __nv_bfloat16 l3b = __float2bfloat16_rn(o.w - __bfloat162float(h3));
    uint2 hp, lp;
    hp.x = (uint32_t)__bfloat16_as_ushort(h0) | ((uint32_t)__bfloat16_as_ushort(h1) << 16);
    hp.y = (uint32_t)__bfloat16_as_ushort(h2) | ((uint32_t)__bfloat16_as_ushort(h3) << 16);
    lp.x = (uint32_t)__bfloat16_as_ushort(l0b) | ((uint32_t)__bfloat16_as_ushort(l1b) << 16);
    lp.y = (uint32_t)__bfloat16_as_ushort(l2b) | ((uint32_t)__bfloat16_as_ushort(l3b) << 16);
    *reinterpret_cast<uint2*>(houthi + nodeBase + off) = hp;
    *reinterpret_cast<uint2*>(houtlo + nodeBase + off) = lp;
    if (houtf) *reinterpret_cast<float4*>(houtf + nodeBase + off) = o;
}

// ---------------- launch ----------------
extern "C" void kernel_launch(void* const* d_in, const int* in_sizes, int n_in,
                              void* d_out, int out_size) {
    const float* x_t       = (const float*)d_in[0];
    const float* time_emb  = (const float*)d_in[1];
    const int*   src       = (const int*)d_in[2];
    const int*   dst       = (const int*)d_in[3];
    const float* W_init    = (const float*)d_in[4];
    const float* b_init    = (const float*)d_in[5];
    const float* Wsrc_down = (const float*)d_in[6];
    const float* bsrc_down = (const float*)d_in[7];
    const float* Wdst_down = (const float*)d_in[8];
    const float* bdst_down = (const float*)d_in[9];
    const float* attn_down = (const float*)d_in[10];
    const float* bout_down = (const float*)d_in[11];
    const float* Wsrc_mid  = (const float*)d_in[12];
    const float* bsrc_mid  = (const float*)d_in[13];
    const float* Wdst_mid  = (const float*)d_in[14];
    const float* bdst_mid  = (const float*)d_in[15];
    const float* attn_mid  = (const float*)d_in[16];
    const float* bout_mid  = (const float*)d_in[17];
    const float* Wsrc_up   = (const float*)d_in[18];
    const float* bsrc_up   = (const float*)d_in[19];
    const float* Wdst_up   = (const float*)d_in[20];
    const float* bdst_up   = (const float*)d_in[21];
    const float* attn_up   = (const float*)d_in[22];
    const float* bout_up   = (const float*)d_in[23];
    const float* W_fin     = (const float*)d_in[24];
    const float* b_fin     = (const float*)d_in[25];

    const int Nn = in_sizes[0] / HID;
    const int E  = in_sizes[2];

    void* pf; cudaGetSymbolAddress(&pf, g_buf);
    void* pi; cudaGetSymbolAddress(&pi, g_ibuf);
    void* pwh; cudaGetSymbolAddress(&pwh, g_whi);
    void* pwl; cudaGetSymbolAddress(&pwl, g_wlo);
    float* base = (float*)pf;
    const size_t SL = (size_t)NPAD * HID;
    float* fs = base + 0 * SL;
    float* fd = base + 1 * SL;
    __nv_bfloat16* hb = (__nv_bfloat16*)(base + 2 * SL);
    const size_t HS = (size_t)NPAD * HID;
    auto Hhi = [&](int i) { return hb + (size_t)i * 2 * HS; };
    auto Hlo = [&](int i) { return hb + (size_t)i * 2 * HS + HS; };

    int* ib = (int*)pi;
    int* deg     = ib;
    int* row_ptr = deg + NN;
    int* cur     = row_ptr + NN + 1;
    int* csr     = cur + NN;
    int* part    = csr + EE;
    __nv_bfloat16* whi = (__nv_bfloat16*)pwh;
    __nv_bfloat16* wlo = (__nv_bfloat16*)pwl;

    float* out = (float*)d_out;
    float* houtf_fin = (out_size >= 2 * Nn * HID) ? (out + (size_t)Nn * HID)
                                                  : (float*)Hhi(2);

    cudaFuncSetAttribute(tgemm_fast<1>, cudaFuncAttributeMaxDynamicSharedMemorySize, TGF_DSM);
    cudaFuncSetAttribute(tgemm_fast<2>, cudaFuncAttributeMaxDynamicSharedMemorySize, TGF_DSM);
    cudaFuncSetAttribute(tgemm_init, cudaFuncAttributeMaxDynamicSharedMemorySize, TGI_DSM);

    dim3 tb(256);
    dim3 tg(512);
    int gE = (E + 255) / 256;
    int gx = (Nn + 127) / 128;
    int gGat = (Nn * 32 + 255) / 256;
    int nBlk = (Nn + 1023) / 1024;

    // ---- capture-safe fork: CSR build on side stream, concurrent with
    // wconv + init GEMM + down0 GEMM on the main stream (R11 schedule).
    cudaStream_t sCsr;
    cudaStreamCreateWithFlags(&sCsr, cudaStreamNonBlocking);
    cudaEvent_t evFork, evJoin;
    cudaEventCreateWithFlags(&evFork, cudaEventDisableTiming);
    cudaEventCreateWithFlags(&evJoin, cudaEventDisableTiming);

    cudaEventRecord(evFork, 0);
    cudaStreamWaitEvent(sCsr, evFork, 0);

    cudaMemsetAsync(deg, 0, sizeof(int) * Nn, sCsr);
    hist_kernel<<<gE, tb, 0, sCsr>>>(dst, deg, E);
    scan_part_kernel<<<nBlk, 1024, 0, sCsr>>>(deg, part, Nn);
    scan_off_kernel<<<1, 32, 0, sCsr>>>(part, nBlk);
    scan_final_kernel<<<nBlk, 1024, 0, sCsr>>>(deg, part, row_ptr, cur, Nn);
    scatter_kernel<<<gE, tb, 0, sCsr>>>(src, dst, cur, csr, E);
    cudaEventRecord(evJoin, sCsr);

    const int OG_INIT = 0, OG_D0 = 32768, OG_D1 = 65536, OG_MID = 98304,
              OG_U0 = 131072, OG_U1 = 196608, OG_FIN = 262144;

    // ---- main stream ----
    wconv_kernel<<<(WTOT + 255) / 256, tb>>>(W_init, Wsrc_down, Wdst_down,
                                             Wsrc_mid, Wdst_mid, Wsrc_up, Wdst_up, W_fin,
                                             whi, wlo);

    tgemm_init<<<gx, tg, TGI_DSM>>>(x_t, time_emb, whi + OG_INIT, wlo + OG_INIT,
                                    b_init, Hhi(0), Hlo(0), Nn);

    tgemm_fast<2><<<gx, tg, TGF_DSM>>>(Hhi(0), Hlo(0), nullptr, nullptr,
                                       whi + OG_D0, wlo + OG_D0, nullptr, fs, fd, Nn, 128);

    cudaStreamWaitEvent(0, evJoin, 0);

    gat_edge_kernel<<<gGat, tb>>>(fs, fd, attn_down, bout_down, bsrc_down, bdst_down,
                                  row_ptr, csr, Hhi(1), Hlo(1), nullptr, Nn);

    tgemm_fast<2><<<gx, tg, TGF_DSM>>>(Hhi(1), Hlo(1), nullptr, nullptr,
                                       whi + OG_D1, wlo + OG_D1, nullptr, fs, fd, Nn, 128);
    gat_edge_kernel<<<gGat, tb>>>(fs, fd, attn_down + HID, bout_down + HID,
                                  bsrc_down + HID, bdst_down + HID, row_ptr, csr,
                                  Hhi(2), Hlo(2), nullptr, Nn);

    tgemm_fast<2><<<gx, tg, TGF_DSM>>>(Hhi(2), Hlo(2), nullptr, nullptr,
                                       whi + OG_MID, wlo + OG_MID, nullptr, fs, fd, Nn, 128);
    gat_edge_kernel<<<gGat, tb>>>(fs, fd, attn_mid, bout_mid, bsrc_mid, bdst_mid,
                                  row_ptr, csr, Hhi(3), Hlo(3), nullptr, Nn);

    tgemm_fast<2><<<gx, tg, TGF_DSM>>>(Hhi(3), Hlo(3), Hhi(1), Hlo(1),
                                       whi + OG_U0, wlo + OG_U0, nullptr, fs, fd, Nn, 256);
    gat_edge_kernel<<<gGat, tb>>>(fs, fd, attn_up, bout_up, bsrc_up, bdst_up,
                                  row_ptr, csr, Hhi(4), Hlo(4), nullptr, Nn);

    tgemm_fast<2><<<gx, tg, TGF_DSM>>>(Hhi(4), Hlo(4), Hhi(0), Hlo(0),
                                       whi + OG_U1, wlo + OG_U1, nullptr, fs, fd, Nn, 256);
    gat_edge_kernel<<<gGat, tb>>>(fs, fd, attn_up + HID, bout_up + HID,
                                  bsrc_up + HID, bdst_up + HID, row_ptr, csr,
                                  Hhi(5), Hlo(5), houtf_fin, Nn);

    tgemm_fast<1><<<gx, tg, TGF_DSM>>>(Hhi(5), Hlo(5), nullptr, nullptr,
                                       whi + OG_FIN, wlo + OG_FIN, b_fin,
                                       out, nullptr, Nn, 128);
    if (houtf_fin != out + (size_t)Nn * HID && out_size >= 2 * Nn * HID) {
        cudaMemcpyAsync(out + (size_t)Nn * HID, houtf_fin,
                        (size_t)Nn * HID * sizeof(float), cudaMemcpyDeviceToDevice);
    }
}

// round 17
// speedup vs baseline: 1.2263x; 1.2260x over previous
#include <cuda_runtime.h>
#include <cuda_bf16.h>
#include <cuda_fp16.h>
#include <mma.h>
#include <math.h>
#include <stdint.h>

using namespace nvcuda;

#define NN 50000
#define NPAD 50048
#define EE 800000
#define HID 128

// ---------------- scratch (no allocation allowed) ----------------
__device__ float g_buf[(size_t)8 * NPAD * HID];
__device__ int g_ibuf[NN + (NN + 1) + NN + EE + 64];
#define WTOT 278528
__device__ __align__(16) __half g_wh[WTOT];   // fp16 weights, transposed [n][k]

__device__ __forceinline__ float gelu_tanh(float x) {
    float x3 = x * x * x;
    float t = tanhf(0.7978845608028654f * (x + 0.044715f * x3));
    return 0.5f * x * (1.0f + t);
}

__device__ __forceinline__ uint32_t smem_u32(const void* p) {
    uint32_t a;
    asm("{ .reg .u64 t; cvta.to.shared.u64 t, %1; cvt.u32.u64 %0, t; }" : "=r"(a) : "l"(p));
    return a;
}
__device__ __forceinline__ void cp_async16(uint32_t dst, const void* src) {
    asm volatile("cp.async.cg.shared.global [%0], [%1], 16;" :: "r"(dst), "l"(src));
}
#define CP_COMMIT() asm volatile("cp.async.commit_group;" ::: "memory")
#define CP_WAIT0()  asm volatile("cp.async.wait_group 0;" ::: "memory")
#define CP_WAIT1()  asm volatile("cp.async.wait_group 1;" ::: "memory")

// ---------------- CSR build ----------------
__global__ void hist_kernel(const int* __restrict__ dst, int* __restrict__ deg, int E) {
    int e = blockIdx.x * blockDim.x + threadIdx.x;
    if (e < E) atomicAdd(&deg[dst[e]], 1);
}

__global__ void scan_part_kernel(const int* __restrict__ deg, int* __restrict__ part, int n) {
    __shared__ int ws[32];
    const int lane = threadIdx.x & 31, wid = threadIdx.x >> 5;
    int i = blockIdx.x * 1024 + threadIdx.x;
    int v = (i < n) ? deg[i] : 0;
#pragma unroll
    for (int o = 16; o; o >>= 1) v += __shfl_xor_sync(0xffffffffu, v, o);
    if (lane == 0) ws[wid] = v;
    __syncthreads();
    if (wid == 0) {
        int x = ws[lane];
#pragma unroll
        for (int o = 16; o; o >>= 1) x += __shfl_xor_sync(0xffffffffu, x, o);
        if (lane == 0) part[blockIdx.x] = x;
    }
}

__global__ void scan_off_kernel(int* __restrict__ part, int nb) {
    int lane = threadIdx.x;
    int v0 = (2 * lane < nb) ? part[2 * lane] : 0;
    int v1 = (2 * lane + 1 < nb) ? part[2 * lane + 1] : 0;
    int sum = v0 + v1;
    int x = sum;
#pragma unroll
    for (int o = 1; o < 32; o <<= 1) {
        int t = __shfl_up_sync(0xffffffffu, x, o);
        if (lane >= o) x += t;
    }
    int excl = x - sum;
    if (2 * lane < nb) part[2 * lane] = excl;
    if (2 * lane + 1 < nb) part[2 * lane + 1] = excl + v0;
}

__global__ void scan_final_kernel(const int* __restrict__ deg, const int* __restrict__ part,
                                  int* __restrict__ row_ptr, int* __restrict__ cur, int n) {
    __shared__ int wsum[32];
    const int lane = threadIdx.x & 31, wid = threadIdx.x >> 5;
    int i = blockIdx.x * 1024 + threadIdx.x;
    int v = (i < n) ? deg[i] : 0;
    int x = v;
#pragma unroll
    for (int o = 1; o < 32; o <<= 1) {
        int t = __shfl_up_sync(0xffffffffu, x, o);
        if (lane >= o) x += t;
    }
    if (lane == 31) wsum[wid] = x;
    __syncthreads();
    if (wid == 0) {
        int y = wsum[lane];
#pragma unroll
        for (int o = 1; o < 32; o <<= 1) {
            int t = __shfl_up_sync(0xffffffffu, y, o);
            if (lane >= o) y += t;
        }
        wsum[lane] = y;
    }
    __syncthreads();
    int off = part[blockIdx.x] + (wid > 0 ? wsum[wid - 1] : 0);
    if (i < n) {
        row_ptr[i + 1] = off + x;
        cur[i] = off + x - v;
    }
    if (i == 0) row_ptr[0] = 0;
}

__global__ void scatter_kernel(const int* __restrict__ src, const int* __restrict__ dst,
                               int* __restrict__ cur, int* __restrict__ csr_src, int E) {
    int e = blockIdx.x * blockDim.x + threadIdx.x;
    if (e < E) {
        int p = atomicAdd(&cur[dst[e]], 1);
        csr_src[p] = src[e];
    }
}

// ---------------- weight transpose + fp16 convert ----------------
__global__ void wconv_kernel(
    const float* __restrict__ Wi,
    const float* __restrict__ Wsd, const float* __restrict__ Wdd,
    const float* __restrict__ Wsm, const float* __restrict__ Wdm,
    const float* __restrict__ Wsu, const float* __restrict__ Wdu,
    const float* __restrict__ Wf,
    __half* __restrict__ wh)
{
    int idx = blockIdx.x * blockDim.x + threadIdx.x;
    if (idx >= WTOT) return;
    int base, K; const float *S, *D2;
    if (idx < 32768)       { base = 0;      K = 256; S = Wi;           D2 = nullptr; }
    else if (idx < 65536)  { base = 32768;  K = 128; S = Wsd;          D2 = Wdd; }
    else if (idx < 98304)  { base = 65536;  K = 128; S = Wsd + 16384;  D2 = Wdd + 16384; }
    else if (idx < 131072) { base = 98304;  K = 128; S = Wsm;          D2 = Wdm; }
    else if (idx < 196608) { base = 131072; K = 256; S = Wsu;          D2 = Wdu; }
    else if (idx < 262144) { base = 196608; K = 256; S = Wsu + 32768;  D2 = Wdu + 32768; }
    else                   { base = 262144; K = 128; S = Wf;           D2 = nullptr; }
    int local = idx - base;
    int n = local / K, k = local - n * K;
    const float* W = (D2 && n >= 128) ? D2 : S;
    int nc = (D2 && n >= 128) ? n - 128 : n;
    wh[idx] = __float2half_rn(W[(size_t)k * 128 + nc]);
}

// ================= tgemm_fast: A fp16 hi/lo, W fp16 single, 2 products =====
// Stage layout (bytes): Ahi[128][40]@0, Alo@10240, W[128*NB][40]@20480.
// STG covers NB=2 (B=20480): 40960; 3 stages = 122880.
#define STG 40960
#define SAH 0
#define SAL 10240
#define SBW 20480
#define TGF_DSM (3 * STG)

template<int NB>
__global__ __launch_bounds__(512) void tgemm_fast(
    const __half* __restrict__ Ahi1, const __half* __restrict__ Alo1,
    const __half* __restrict__ Ahi2, const __half* __restrict__ Alo2,
    const __half* __restrict__ Wp,
    const float* __restrict__ bias,
    float* __restrict__ Ca, float* __restrict__ Cb,
    int M, int K)
{
    extern __shared__ char dsm[];
    const uint32_t sb = smem_u32(dsm);
    const int tid = threadIdx.x;
    const int wid = tid >> 5, lane = tid & 31;
    const int rowBase = blockIdx.x * 128;

    __shared__ float sBias[128];
    if (NB == 1 && tid < 128) sBias[tid] = bias[tid];

    auto cpAll = [&](int st, int c) {
        {
            const __half* Ah = (c < 4) ? Ahi1 : Ahi2;
            const __half* Al = (c < 4) ? Alo1 : Alo2;
            int cc = c & 3;
            int r = tid >> 2, q = tid & 3;
            size_t so = (size_t)(rowBase + r) * 128 + cc * 32 + q * 8;
            uint32_t d = sb + st * STG + r * 80 + (q << 4);
            cp_async16(d + SAH, Ah + so);
            cp_async16(d + SAL, Al + so);
        }
        if (NB == 2) {
            int r = tid >> 1, q = tid & 1;
#pragma unroll
            for (int dq = 0; dq < 2; dq++) {
                int qq = q * 2 + dq;
                uint32_t d = sb + st * STG + SBW + r * 80 + (qq << 4);
                cp_async16(d, Wp + (size_t)r * K + (c << 5) + (qq << 3));
            }
        } else {
            int r = tid >> 2, q = tid & 3;
            uint32_t d = sb + st * STG + SBW + r * 80 + (q << 4);
            cp_async16(d, Wp + (size_t)r * K + (c << 5) + (q << 3));
        }
    };

    const int nCh = K >> 5;

    cpAll(0, 0); CP_COMMIT();
    if (nCh > 1) { cpAll(1, 1); CP_COMMIT(); }

    if (NB == 2) {
        const int rowg = wid & 3;
        const int colh = (wid >> 2) & 1;
        const int hb   = wid >> 3;
        wmma::fragment<wmma::accumulator, 16, 16, 16, float> acc[8];
#pragma unroll
        for (int t = 0; t < 8; t++) wmma::fill_fragment(acc[t], 0.0f);

        for (int c = 0; c < nCh; c++) {
            if (c + 1 == nCh) { CP_WAIT0(); } else { CP_WAIT1(); }
            __syncthreads();
            const int st = c % 3;
            const __half* ah_base = reinterpret_cast<const __half*>(dsm + st * STG + SAH);
            const __half* al_base = reinterpret_cast<const __half*>(dsm + st * STG + SAL);
            const __half* bw_base = reinterpret_cast<const __half*>(dsm + st * STG + SBW);
#pragma unroll
            for (int ks = 0; ks < 32; ks += 16) {
                wmma::fragment<wmma::matrix_a, 16, 16, 16, half, wmma::row_major> ah0, ah1, al0, al1;
                wmma::load_matrix_sync(ah0, ah_base + (rowg * 32) * 40 + ks, 40);
                wmma::load_matrix_sync(ah1, ah_base + (rowg * 32 + 16) * 40 + ks, 40);
                wmma::load_matrix_sync(al0, al_base + (rowg * 32) * 40 + ks, 40);
                wmma::load_matrix_sync(al1, al_base + (rowg * 32 + 16) * 40 + ks, 40);
#pragma unroll
                for (int t = 0; t < 4; t++) {
                    int brow = hb * 128 + colh * 64 + t * 16;
                    wmma::fragment<wmma::matrix_b, 16, 16, 16, half, wmma::col_major> bw;
                    wmma::load_matrix_sync(bw, bw_base + brow * 40 + ks, 40);
                    wmma::mma_sync(acc[t], ah0, bw, acc[t]);
                    wmma::mma_sync(acc[t], al0, bw, acc[t]);
                    wmma::mma_sync(acc[4 + t], ah1, bw, acc[4 + t]);
                    wmma::mma_sync(acc[4 + t], al1, bw, acc[4 + t]);
                }
            }
            if (c + 2 < nCh) { cpAll((c + 2) % 3, c + 2); CP_COMMIT(); }
        }
        float* Cp = hb ? Cb : Ca;
#pragma unroll
        for (int s = 0; s < 2; s++) {
#pragma unroll
            for (int t = 0; t < 4; t++) {
                wmma::store_matrix_sync(
                    Cp + (size_t)(rowBase + rowg * 32 + s * 16) * 128 + colh * 64 + t * 16,
                    acc[s * 4 + t], 128, wmma::mem_row_major);
            }
        }
    } else {
        const int stripe = wid >> 1, colh = wid & 1;
        wmma::fragment<wmma::accumulator, 16, 16, 16, float> acc[4];
#pragma unroll
        for (int t = 0; t < 4; t++) wmma::fill_fragment(acc[t], 0.0f);

        for (int c = 0; c < nCh; c++) {
            if (c + 1 == nCh) { CP_WAIT0(); } else { CP_WAIT1(); }
            __syncthreads();
            const int st = c % 3;
            const __half* ah_base = reinterpret_cast<const __half*>(dsm + st * STG + SAH);
            const __half* al_base = reinterpret_cast<const __half*>(dsm + st * STG + SAL);
            const __half* bw_base = reinterpret_cast<const __half*>(dsm + st * STG + SBW);
#pragma unroll
            for (int ks = 0; ks < 32; ks += 16) {
                wmma::fragment<wmma::matrix_a, 16, 16, 16, half, wmma::row_major> ah, al;
                wmma::load_matrix_sync(ah, ah_base + stripe * 16 * 40 + ks, 40);
                wmma::load_matrix_sync(al, al_base + stripe * 16 * 40 + ks, 40);
#pragma unroll
                for (int t = 0; t < 4; t++) {
                    int brow = colh * 64 + t * 16;
                    wmma::fragment<wmma::matrix_b, 16, 16, 16, half, wmma::col_major> bw;
                    wmma::load_matrix_sync(bw, bw_base + brow * 40 + ks, 40);
                    wmma::mma_sync(acc[t], ah, bw, acc[t]);
                    wmma::mma_sync(acc[t], al, bw, acc[t]);
                }
            }
            if (c + 2 < nCh) { cpAll((c + 2) % 3, c + 2); CP_COMMIT(); }
        }

        __syncthreads();
        float* sE = reinterpret_cast<float*>(dsm) + wid * 256;
#pragma unroll
        for (int t = 0; t < 4; t++) {
            int tg = colh * 4 + t;
            wmma::store_matrix_sync(sE, acc[t], 16, wmma::mem_row_major);
            __syncwarp();
#pragma unroll
            for (int i = 0; i < 8; i++) {
                int idx = i * 32 + lane;
                int row = idx >> 4, col = idx & 15;
                int r = rowBase + stripe * 16 + row;
                if (r < M) {
                    float vv = sE[idx] + sBias[tg * 16 + col];
                    Ca[(size_t)r * 128 + tg * 16 + col] = vv;
                }
            }
            __syncwarp();
        }
    }
}

// ================= tgemm_init: A fp32 -> fp16 hi/lo in smem, W fp16 ========
#define STGI 30720
#define IAH 0
#define IAL 10240
#define IBW 20480
#define TGI_DSM (2 * STGI)

__global__ __launch_bounds__(512) void tgemm_init(
    const float* __restrict__ A1, const float* __restrict__ A2,
    const __half* __restrict__ Wp,
    const float* __restrict__ bias,
    __half* __restrict__ Chi, __half* __restrict__ Clo,
    int M)
{
    const int K = 256;
    extern __shared__ char dsm[];
    const uint32_t sb = smem_u32(dsm);
    const int tid = threadIdx.x;
    const int wid = tid >> 5, lane = tid & 31;
    const int rowBase = blockIdx.x * 128;

    __shared__ float sBias[128];
    if (tid < 128) sBias[tid] = bias[tid];

    const int ar = tid >> 2, ks8 = (tid & 3) << 3;
    const int grow = rowBase + ar;

    float v[8];
    auto loadA = [&](int c) {
        int kg = (c << 5) + ks8;
        if (grow < M) {
            const float* Ap; int kl;
            if (kg < 128) { Ap = A1; kl = kg; } else { Ap = A2; kl = kg - 128; }
            const float4* p = reinterpret_cast<const float4*>(Ap + (size_t)grow * 128 + kl);
            float4 q0 = p[0], q1 = p[1];
            v[0] = q0.x; v[1] = q0.y; v[2] = q0.z; v[3] = q0.w;
            v[4] = q1.x; v[5] = q1.y; v[6] = q1.z; v[7] = q1.w;
        } else {
#pragma unroll
            for (int i = 0; i < 8; i++) v[i] = 0.0f;
        }
    };
    auto storeA = [&](int st) {
        uint32_t hw[4], lw[4];
#pragma unroll
        for (int j = 0; j < 4; j++) {
            float x0 = v[j * 2], x1 = v[j * 2 + 1];
            __half h0 = __float2half_rn(x0);
            __half h1 = __float2half_rn(x1);
            __half l0 = __float2half_rn(x0 - __half2float(h0));
            __half l1 = __float2half_rn(x1 - __half2float(h1));
            hw[j] = (uint32_t)__half_as_ushort(h0) | ((uint32_t)__half_as_ushort(h1) << 16);
            lw[j] = (uint32_t)__half_as_ushort(l0) | ((uint32_t)__half_as_ushort(l1) << 16);
        }
        char* basep = dsm + st * STGI;
        int off = ar * 80 + ks8 * 2;
        *reinterpret_cast<uint4*>(basep + IAH + off) = make_uint4(hw[0], hw[1], hw[2], hw[3]);
        *reinterpret_cast<uint4*>(basep + IAL + off) = make_uint4(lw[0], lw[1], lw[2], lw[3]);
    };
    auto cpB = [&](int st, int c) {
        int r = tid >> 2, q = tid & 3;
        uint32_t d = sb + st * STGI + IBW + r * 80 + (q << 4);
        cp_async16(d, Wp + (size_t)r * K + (c << 5) + (q << 3));
    };

    loadA(0);
    cpB(0, 0);
    storeA(0);
    CP_COMMIT();
    CP_WAIT0();
    __syncthreads();

    const int stripe = wid >> 1, colh = wid & 1;
    wmma::fragment<wmma::accumulator, 16, 16, 16, float> acc[4];
#pragma unroll
    for (int t = 0; t < 4; t++) wmma::fill_fragment(acc[t], 0.0f);

    const int nCh = K >> 5;
    for (int c = 0; c < nCh; c++) {
        const int cur = c & 1;
        const bool more = (c + 1 < nCh);
        if (more) {
            loadA(c + 1);
            cpB(cur ^ 1, c + 1);
            CP_COMMIT();
        }
        const __half* ah_base = reinterpret_cast<const __half*>(dsm + cur * STGI + IAH);
        const __half* al_base = reinterpret_cast<const __half*>(dsm + cur * STGI + IAL);
        const __half* bw_base = reinterpret_cast<const __half*>(dsm + cur * STGI + IBW);
#pragma unroll
        for (int ks = 0; ks < 32; ks += 16) {
            wmma::fragment<wmma::matrix_a, 16, 16, 16, half, wmma::row_major> ah, al;
            wmma::load_matrix_sync(ah, ah_base + stripe * 16 * 40 + ks, 40);
            wmma::load_matrix_sync(al, al_base + stripe * 16 * 40 + ks, 40);
#pragma unroll
            for (int t = 0; t < 4; t++) {
                int brow = colh * 64 + t * 16;
                wmma::fragment<wmma::matrix_b, 16, 16, 16, half, wmma::col_major> bw;
                wmma::load_matrix_sync(bw, bw_base + brow * 40 + ks, 40);
                wmma::mma_sync(acc[t], ah, bw, acc[t]);
                wmma::mma_sync(acc[t], al, bw, acc[t]);
            }
        }
        if (more) {
            storeA(cur ^ 1);
            CP_WAIT0();
            __syncthreads();
        }
    }

    __syncthreads();
    float* sE = reinterpret_cast<float*>(dsm) + wid * 256;
#pragma unroll
    for (int t = 0; t < 4; t++) {
        int tg = colh * 4 + t;
        wmma::store_matrix_sync(sE, acc[t], 16, wmma::mem_row_major);
        __syncwarp();
#pragma unroll
        for (int i = 0; i < 8; i++) {
            int idx = i * 32 + lane;
            int row = idx >> 4, col = idx & 15;
            int r = rowBase + stripe * 16 + row;
            float vv = gelu_tanh(sE[idx] + sBias[tg * 16 + col]);
            __half hh = __float2half_rn(vv);
            __half ll = __float2half_rn(vv - __half2float(hh));
            size_t o = (size_t)r * 128 + tg * 16 + col;
            Chi[o] = hh;
            Clo[o] = ll;
        }
        __syncwarp();
    }
}

// ---------------- GATv2 edge aggregation (warp per dst node) ----------------
__device__ __forceinline__ float edge_logit(float4 f, float4 fdv, float4 attnv) {
    float4 ev;
    ev.x = f.x + fdv.x; ev.x = (ev.x > 0.f) ? ev.x : 0.2f * ev.x;
    ev.y = f.y + fdv.y; ev.y = (ev.y > 0.f) ? ev.y : 0.2f * ev.y;
    ev.z = f.z + fdv.z; ev.z = (ev.z > 0.f) ? ev.z : 0.2f * ev.z;
    ev.w = f.w + fdv.w; ev.w = (ev.w > 0.f) ? ev.w : 0.2f * ev.w;
    return ev.x * attnv.x + ev.y * attnv.y + ev.z * attnv.z + ev.w * attnv.w;
}

__global__ __launch_bounds__(256) void gat_edge_kernel(
    const float* __restrict__ fs, const float* __restrict__ fd,
    const float* __restrict__ attn, const float* __restrict__ bout,
    const float* __restrict__ bsrc, const float* __restrict__ bdst,
    const int* __restrict__ row_ptr, const int* __restrict__ csr_src,
    __half* __restrict__ houthi, __half* __restrict__ houtlo,
    float* __restrict__ houtf, int n_nodes)
{
    const int warp = (blockIdx.x * blockDim.x + threadIdx.x) >> 5;
    const int lane = threadIdx.x & 31;
    if (warp >= n_nodes) return;

    const int off = lane * 4;
    const size_t nodeBase = (size_t)warp * 128;

    const float4 bsv = *reinterpret_cast<const float4*>(bsrc + off);
    const float4 bdv = *reinterpret_cast<const float4*>(bdst + off);
    float4 fdv = *reinterpret_cast<const float4*>(fd + nodeBase + off);
    fdv.x += bsv.x + bdv.x; fdv.y += bsv.y + bdv.y;
    fdv.z += bsv.z + bdv.z; fdv.w += bsv.w + bdv.w;
    const float4 attnv = *reinterpret_cast<const float4*>(attn + off);

    float s = 0.0f;
    float4 acc = make_float4(0.f, 0.f, 0.f, 0.f);

    int e = row_ptr[warp];
    const int end = row_ptr[warp + 1];

    for (; e + 8 <= end; e += 8) {
        float4 f[8];
        float l[8];
#pragma unroll
        for (int j = 0; j < 8; j++) {
            int ij = csr_src[e + j];
            f[j] = *reinterpret_cast<const float4*>(fs + (size_t)ij * 128 + off);
        }
#pragma unroll
        for (int j = 0; j < 8; j++) l[j] = edge_logit(f[j], fdv, attnv);
#pragma unroll
        for (int j = 0; j < 8; j++) l[j] += __shfl_xor_sync(0xffffffffu, l[j], 1);
#pragma unroll
        for (int j = 0; j < 8; j++) l[j] += __shfl_xor_sync(0xffffffffu, l[j], 2);
#pragma unroll
        for (int j = 0; j < 8; j++) l[j] += __shfl_xor_sync(0xffffffffu, l[j], 4);
#pragma unroll
        for (int j = 0; j < 8; j++) {
            float p = __expf(fminf(l[j], 80.f));
            s += p;
            acc.x = fmaf(p, f[j].x, acc.x);
            acc.y = fmaf(p, f[j].y, acc.y);
            acc.z = fmaf(p, f[j].z, acc.z);
            acc.w = fmaf(p, f[j].w, acc.w);
        }
    }
    for (; e + 4 <= end; e += 4) {
        float4 f[4];
        float l[4];
#pragma unroll
        for (int j = 0; j < 4; j++) {
            int ij = csr_src[e + j];
            f[j] = *reinterpret_cast<const float4*>(fs + (size_t)ij * 128 + off);
        }
#pragma unroll
        for (int j = 0; j < 4; j++) l[j] = edge_logit(f[j], fdv, attnv);
#pragma unroll
        for (int j = 0; j < 4; j++) l[j] += __shfl_xor_sync(0xffffffffu, l[j], 1);
#pragma unroll
        for (int j = 0; j < 4; j++) l[j] += __shfl_xor_sync(0xffffffffu, l[j], 2);
#pragma unroll
        for (int j = 0; j < 4; j++) l[j] += __shfl_xor_sync(0xffffffffu, l[j], 4);
#pragma unroll
        for (int j = 0; j < 4; j++) {
            float p = __expf(fminf(l[j], 80.f));
            s += p;
            acc.x = fmaf(p, f[j].x, acc.x);
            acc.y = fmaf(p, f[j].y, acc.y);
            acc.z = fmaf(p, f[j].z, acc.z);
            acc.w = fmaf(p, f[j].w, acc.w);
        }
    }
    for (; e < end; e++) {
        int i0 = csr_src[e];
        float4 f0 = *reinterpret_cast<const float4*>(fs + (size_t)i0 * 128 + off);
        float l0 = edge_logit(f0, fdv, attnv);
        l0 += __shfl_xor_sync(0xffffffffu, l0, 1);
        l0 += __shfl_xor_sync(0xffffffffu, l0, 2);
        l0 += __shfl_xor_sync(0xffffffffu, l0, 4);
        float p0 = __expf(fminf(l0, 80.f));
        s += p0;
        acc.x = fmaf(p0, f0.x, acc.x);
        acc.y = fmaf(p0, f0.y, acc.y);
        acc.z = fmaf(p0, f0.z, acc.z);
        acc.w = fmaf(p0, f0.w, acc.w);
    }

    const float4 bv = *reinterpret_cast<const float4*>(bout + off);
    float inv = 1.0f / (s + 1e-9f);
    float salpha = s * inv;
    float4 o;
    o.x = gelu_tanh(acc.x * inv + bsv.x * salpha + bv.x);
    o.y = gelu_tanh(acc.y * inv + bsv.y * salpha + bv.y);
    o.z = gelu_tanh(acc.z * inv + bsv.z * salpha + bv.z);
    o.w = gelu_tanh(acc.w * inv + bsv.w * salpha + bv.w);

    __half h0 = __float2half_rn(o.x), h1 = __float2half_rn(o.y);
    __half h2 = __float2half_rn(o.z), h3 = __float2half_rn(o.w);
    __half l0b = __float2half_rn(o.x - __half2float(h0));
    __half l1b = __float2half_rn(o.y - __half2float(h1));
    __half l2b = __float2half_rn(o.z - __half2float(h2));
    __half l3b = __float2half_rn(o.w - __half2float(h3));
    uint2 hp, lp;
    hp.x = (uint32_t)__half_as_ushort(h0) | ((uint32_t)__half_as_ushort(h1) << 16);
    hp.y = (uint32_t)__half_as_ushort(h2) | ((uint32_t)__half_as_ushort(h3) << 16);
    lp.x = (uint32_t)__half_as_ushort(l0b) | ((uint32_t)__half_as_ushort(l1b) << 16);
    lp.y = (uint32_t)__half_as_ushort(l2b) | ((uint32_t)__half_as_ushort(l3b) << 16);
    *reinterpret_cast<uint2*>(houthi + nodeBase + off) = hp;
    *reinterpret_cast<uint2*>(houtlo + nodeBase + off) = lp;
    if (houtf) *reinterpret_cast<float4*>(houtf + nodeBase + off) = o;
}

// ---------------- launch ----------------
extern "C" void kernel_launch(void* const* d_in, const int* in_sizes, int n_in,
                              void* d_out, int out_size) {
    const float* x_t       = (const float*)d_in[0];
    const float* time_emb  = (const float*)d_in[1];
    const int*   src       = (const int*)d_in[2];
    const int*   dst       = (const int*)d_in[3];
    const float* W_init    = (const float*)d_in[4];
    const float* b_init    = (const float*)d_in[5];
    const float* Wsrc_down = (const float*)d_in[6];
    const float* bsrc_down = (const float*)d_in[7];
    const float* Wdst_down = (const float*)d_in[8];
    const float* bdst_down = (const float*)d_in[9];
    const float* attn_down = (const float*)d_in[10];
    const float* bout_down = (const float*)d_in[11];
    const float* Wsrc_mid  = (const float*)d_in[12];
    const float* bsrc_mid  = (const float*)d_in[13];
    const float* Wdst_mid  = (const float*)d_in[14];
    const float* bdst_mid  = (const float*)d_in[15];
    const float* attn_mid  = (const float*)d_in[16];
    const float* bout_mid  = (const float*)d_in[17];
    const float* Wsrc_up   = (const float*)d_in[18];
    const float* bsrc_up   = (const float*)d_in[19];
    const float* Wdst_up   = (const float*)d_in[20];
    const float* bdst_up   = (const float*)d_in[21];
    const float* attn_up   = (const float*)d_in[22];
    const float* bout_up   = (const float*)d_in[23];
    const float* W_fin     = (const float*)d_in[24];
    const float* b_fin     = (const float*)d_in[25];

    const int Nn = in_sizes[0] / HID;
    const int E  = in_sizes[2];

    void* pf; cudaGetSymbolAddress(&pf, g_buf);
    void* pi; cudaGetSymbolAddress(&pi, g_ibuf);
    void* pwh; cudaGetSymbolAddress(&pwh, g_wh);
    float* base = (float*)pf;
    const size_t SL = (size_t)NPAD * HID;
    float* fs = base + 0 * SL;
    float* fd = base + 1 * SL;
    __half* hb = (__half*)(base + 2 * SL);
    const size_t HS = (size_t)NPAD * HID;
    auto Hhi = [&](int i) { return hb + (size_t)i * 2 * HS; };
    auto Hlo = [&](int i) { return hb + (size_t)i * 2 * HS + HS; };

    int* ib = (int*)pi;
    int* deg     = ib;
    int* row_ptr = deg + NN;
    int* cur     = row_ptr + NN + 1;
    int* csr     = cur + NN;
    int* part    = csr + EE;
    __half* wh = (__half*)pwh;

    float* out = (float*)d_out;
    float* houtf_fin = (out_size >= 2 * Nn * HID) ? (out + (size_t)Nn * HID)
                                                  : (float*)Hhi(2);

    cudaFuncSetAttribute(tgemm_fast<1>, cudaFuncAttributeMaxDynamicSharedMemorySize, TGF_DSM);
    cudaFuncSetAttribute(tgemm_fast<2>, cudaFuncAttributeMaxDynamicSharedMemorySize, TGF_DSM);
    cudaFuncSetAttribute(tgemm_init, cudaFuncAttributeMaxDynamicSharedMemorySize, TGI_DSM);

    dim3 tb(256);
    dim3 tg(512);
    int gE = (E + 255) / 256;
    int gx = (Nn + 127) / 128;
    int gGat = (Nn * 32 + 255) / 256;
    int nBlk = (Nn + 1023) / 1024;

    // ---- capture-safe fork: CSR build on side stream (R11 schedule) ----
    cudaStream_t sCsr;
    cudaStreamCreateWithFlags(&sCsr, cudaStreamNonBlocking);
    cudaEvent_t evFork, evJoin;
    cudaEventCreateWithFlags(&evFork, cudaEventDisableTiming);
    cudaEventCreateWithFlags(&evJoin, cudaEventDisableTiming);

    cudaEventRecord(evFork, 0);
    cudaStreamWaitEvent(sCsr, evFork, 0);

    cudaMemsetAsync(deg, 0, sizeof(int) * Nn, sCsr);
    hist_kernel<<<gE, tb, 0, sCsr>>>(dst, deg, E);
    scan_part_kernel<<<nBlk, 1024, 0, sCsr>>>(deg, part, Nn);
    scan_off_kernel<<<1, 32, 0, sCsr>>>(part, nBlk);
    scan_final_kernel<<<nBlk, 1024, 0, sCsr>>>(deg, part, row_ptr, cur, Nn);
    scatter_kernel<<<gE, tb, 0, sCsr>>>(src, dst, cur, csr, E);
    cudaEventRecord(evJoin, sCsr);

    const int OG_INIT = 0, OG_D0 = 32768, OG_D1 = 65536, OG_MID = 98304,
              OG_U0 = 131072, OG_U1 = 196608, OG_FIN = 262144;

    // ---- main stream ----
    wconv_kernel<<<(WTOT + 255) / 256, tb>>>(W_init, Wsrc_down, Wdst_down,
                                             Wsrc_mid, Wdst_mid, Wsrc_up, Wdst_up, W_fin,
                                             wh);

    tgemm_init<<<gx, tg, TGI_DSM>>>(x_t, time_emb, wh + OG_INIT,
                                    b_init, Hhi(0), Hlo(0), Nn);

    tgemm_fast<2><<<gx, tg, TGF_DSM>>>(Hhi(0), Hlo(0), nullptr, nullptr,
                                       wh + OG_D0, nullptr, fs, fd, Nn, 128);

    cudaStreamWaitEvent(0, evJoin, 0);

    gat_edge_kernel<<<gGat, tb>>>(fs, fd, attn_down, bout_down, bsrc_down, bdst_down,
                                  row_ptr, csr, Hhi(1), Hlo(1), nullptr, Nn);

    tgemm_fast<2><<<gx, tg, TGF_DSM>>>(Hhi(1), Hlo(1), nullptr, nullptr,
                                       wh + OG_D1, nullptr, fs, fd, Nn, 128);
    gat_edge_kernel<<<gGat, tb>>>(fs, fd, attn_down + HID, bout_down + HID,
                                  bsrc_down + HID, bdst_down + HID, row_ptr, csr,
                                  Hhi(2), Hlo(2), nullptr, Nn);

    tgemm_fast<2><<<gx, tg, TGF_DSM>>>(Hhi(2), Hlo(2), nullptr, nullptr,
                                       wh + OG_MID, nullptr, fs, fd, Nn, 128);
    gat_edge_kernel<<<gGat, tb>>>(fs, fd, attn_mid, bout_mid, bsrc_mid, bdst_mid,
                                  row_ptr, csr, Hhi(3), Hlo(3), nullptr, Nn);

    tgemm_fast<2><<<gx, tg, TGF_DSM>>>(Hhi(3), Hlo(3), Hhi(1), Hlo(1),
                                       wh + OG_U0, nullptr, fs, fd, Nn, 256);
    gat_edge_kernel<<<gGat, tb>>>(fs, fd, attn_up, bout_up, bsrc_up, bdst_up,
                                  row_ptr, csr, Hhi(4), Hlo(4), nullptr, Nn);

    tgemm_fast<2><<<gx, tg, TGF_DSM>>>(Hhi(4), Hlo(4), Hhi(0), Hlo(0),
                                       wh + OG_U1, nullptr, fs, fd, Nn, 256);
    gat_edge_kernel<<<gGat, tb>>>(fs, fd, attn_up + HID, bout_up + HID,
                                  bsrc_up + HID, bdst_up + HID, row_ptr, csr,
                                  Hhi(5), Hlo(5), houtf_fin, Nn);

    tgemm_fast<1><<<gx, tg, TGF_DSM>>>(Hhi(5), Hlo(5), nullptr, nullptr,
                                       wh + OG_FIN, b_fin,
                                       out, nullptr, Nn, 128);
    if (houtf_fin != out + (size_t)Nn * HID && out_size >= 2 * Nn * HID) {
        cudaMemcpyAsync(out + (size_t)Nn * HID, houtf_fin,
                        (size_t)Nn * HID * sizeof(float), cudaMemcpyDeviceToDevice);
    }
}